// round 9
// baseline (speedup 1.0000x reference)
#include <cuda_runtime.h>
#include <cuda_bf16.h>
#include <cstdint>

#define S_LEN 4096
#define HID   1024
#define HEADS 16
#define HDIM  64
#define NBLK  4

__device__ __nv_bfloat16 g_Xh[S_LEN * HID], g_Xl[S_LEN * HID];
__device__ __nv_bfloat16 g_Qh[S_LEN * HID], g_Ql[S_LEN * HID];  // [h][s][d]
__device__ __nv_bfloat16 g_Kh[S_LEN * HID], g_Kl[S_LEN * HID];  // [h][s][d]
__device__ __nv_bfloat16 g_Vh[S_LEN * HID], g_Vl[S_LEN * HID];  // [h][d][s]
__device__ __nv_bfloat16 g_Ah[S_LEN * HID], g_Al[S_LEN * HID];  // [s][hid]
__device__ __nv_bfloat16 g_Wh[4][HID * HID], g_Wl[4][HID * HID];

__device__ __forceinline__ uint32_t smem_u32(const void* p) {
    uint32_t a;
    asm("{ .reg .u64 t; cvta.to.shared.u64 t, %1; cvt.u32.u64 %0, t; }" : "=r"(a) : "l"(p));
    return a;
}
#define CP_ASYNC16(dst, src) \
    asm volatile("cp.async.cg.shared.global [%0], [%1], 16;" :: "r"(dst), "l"(src))
#define CP_COMMIT() asm volatile("cp.async.commit_group;" ::: "memory")
#define CP_WAIT0()  asm volatile("cp.async.wait_group 0;" ::: "memory")
#define CP_WAIT1()  asm volatile("cp.async.wait_group 1;" ::: "memory")
#define LDSM_X4(r0, r1, r2, r3, addr) \
    asm volatile("ldmatrix.sync.aligned.m8n8.x4.shared.b16 {%0,%1,%2,%3}, [%4];" \
                 : "=r"(r0), "=r"(r1), "=r"(r2), "=r"(r3) : "r"(addr))
#define MMA16816(d, a, b) \
    asm volatile("mma.sync.aligned.m16n8k16.row.col.f32.bf16.bf16.f32 " \
                 "{%0,%1,%2,%3}, {%4,%5,%6,%7}, {%8,%9}, {%0,%1,%2,%3};" \
                 : "+f"((d)[0]), "+f"((d)[1]), "+f"((d)[2]), "+f"((d)[3]) \
                 : "r"((a)[0]), "r"((a)[1]), "r"((a)[2]), "r"((a)[3]), \
                   "r"((b)[0]), "r"((b)[1]))

__device__ __forceinline__ uint32_t packbf2(float a, float b) {
    uint32_t r;
    asm("cvt.rn.bf16x2.f32 %0, %1, %2;" : "=r"(r) : "f"(b), "f"(a));
    return r;
}
__device__ __forceinline__ float bflow(uint32_t p)  { return __uint_as_float(p << 16); }
__device__ __forceinline__ float bfhigh(uint32_t p) { return __uint_as_float(p & 0xffff0000u); }
__device__ __forceinline__ uint32_t packsc(float s) {
    float hf = __bfloat162float(__float2bfloat16(s));
    return packbf2(s, s - hf);
}
__device__ __forceinline__ float fex2(float x) {
    float e;
    asm("ex2.approx.f32 %0, %1;" : "=f"(e) : "f"(x));
    return e;
}

// ---------------- conversions ----------------
__global__ __launch_bounds__(256) void convhl_k(const float* __restrict__ X,
                                                __nv_bfloat16* __restrict__ H,
                                                __nv_bfloat16* __restrict__ L)
{
    int i = (blockIdx.x * 256 + threadIdx.x) * 4;
    float4 v = *reinterpret_cast<const float4*>(X + i);
    float f[4] = {v.x, v.y, v.z, v.w};
    __nv_bfloat16 h[4], l[4];
#pragma unroll
    for (int j = 0; j < 4; j++) {
        h[j] = __float2bfloat16(f[j]);
        l[j] = __float2bfloat16(f[j] - __bfloat162float(h[j]));
    }
    *reinterpret_cast<uint2*>(H + i) = *reinterpret_cast<uint2*>(h);
    *reinterpret_cast<uint2*>(L + i) = *reinterpret_cast<uint2*>(l);
}

__global__ __launch_bounds__(256) void convwt_k(const float* __restrict__ w0,
                                                const float* __restrict__ w1,
                                                const float* __restrict__ w2,
                                                const float* __restrict__ w3,
                                                __nv_bfloat16* __restrict__ HtB,
                                                __nv_bfloat16* __restrict__ LtB)
{
    __shared__ float t[32][33];
    const int z = blockIdx.z;
    const float* W = (z == 0) ? w0 : (z == 1) ? w1 : (z == 2) ? w2 : w3;
    __nv_bfloat16* Ht = HtB + (size_t)z * HID * HID;
    __nv_bfloat16* Lt = LtB + (size_t)z * HID * HID;
    int n0 = blockIdx.x * 32, k0 = blockIdx.y * 32;
    int tx = threadIdx.x & 31, ty = threadIdx.x >> 5;
#pragma unroll
    for (int s = 0; s < 32; s += 8)
        t[ty + s][tx] = W[(size_t)(k0 + ty + s) * HID + n0 + tx];
    __syncthreads();
#pragma unroll
    for (int s = 0; s < 32; s += 8) {
        float v = t[tx][ty + s];
        __nv_bfloat16 h = __float2bfloat16(v);
        __nv_bfloat16 l = __float2bfloat16(v - __bfloat162float(h));
        size_t o = (size_t)(n0 + ty + s) * HID + k0 + tx;
        Ht[o] = h; Lt[o] = l;
    }
}

// ---------------- HMMA 3-term GEMM (single-sync pipeline) ----------------
// qkv=1: grid.z in {0,1,2} selects weight + epilogue (Q/K mode1, V mode2)
// qkv=0: epilogue mode0, fp32 C
#define GKC  32
#define GNC  (HID / GKC)
#define ARRB (128 * 80)
#define BUFB (4 * ARRB)
#define EPIP 129

__global__ __launch_bounds__(256) void gemmmma_k(const __nv_bfloat16* __restrict__ Ap,
                                                 const __nv_bfloat16* __restrict__ Alp,
                                                 const __nv_bfloat16* __restrict__ WhB,
                                                 const __nv_bfloat16* __restrict__ WlB,
                                                 float* __restrict__ C,
                                                 __nv_bfloat16* __restrict__ Qh,
                                                 __nv_bfloat16* __restrict__ Ql,
                                                 __nv_bfloat16* __restrict__ Kh,
                                                 __nv_bfloat16* __restrict__ Kl,
                                                 __nv_bfloat16* __restrict__ Vh,
                                                 __nv_bfloat16* __restrict__ Vl,
                                                 int qkv)
{
    extern __shared__ char dsm[];
    const uint32_t sbase = smem_u32(dsm);
    const int tid = threadIdx.x, wid = tid >> 5, lane = tid & 31;
    const int m0 = blockIdx.y * 128, n0 = blockIdx.x * 128;
    const int m0w = (wid & 1) * 64, n0w = (wid >> 1) * 32;
    const int z = qkv ? blockIdx.z : 0;
    const __nv_bfloat16* Bp  = WhB + (size_t)z * HID * HID;
    const __nv_bfloat16* Blp = WlB + (size_t)z * HID * HID;

    float acc[4][4][4];
#pragma unroll
    for (int i = 0; i < 4; i++)
#pragma unroll
        for (int j = 0; j < 4; j++)
#pragma unroll
            for (int r = 0; r < 4; r++) acc[i][j][r] = 0.f;

    auto load_chunk = [&](int c, int b) {
        const int koff = c * GKC;
        const uint32_t dst0 = sbase + b * BUFB;
#pragma unroll
        for (int l = 0; l < 8; l++) {
            int e = tid + l * 256;
            int arr = e >> 9, r = (e >> 2) & 127, q = e & 3;
            const __nv_bfloat16* G = (arr == 0) ? Ap : (arr == 1) ? Alp
                                   : (arr == 2) ? Bp : Blp;
            int t0 = (arr < 2) ? m0 : n0;
            CP_ASYNC16(dst0 + arr * ARRB + r * 80 + q * 16,
                       G + (size_t)(t0 + r) * HID + koff + q * 8);
        }
    };

    load_chunk(0, 0);
    CP_COMMIT();

    const int arow = lane & 15, acolb = (lane >> 4) * 16;
    const int brow = ((lane >> 4) << 3) + (lane & 7);
    const int bcolb = ((lane >> 3) & 1) * 16;

    for (int c = 0; c < GNC; c++) {
        const int b = c & 1;
        CP_WAIT0();
        __syncthreads();
        if (c + 1 < GNC) { load_chunk(c + 1, (c + 1) & 1); CP_COMMIT(); }

        const uint32_t bufb = sbase + b * BUFB;
#pragma unroll
        for (int kk = 0; kk < 2; kk++) {
            uint32_t ah[4][4], al[4][4], bh[4][2], bl[4][2];
            const int kb = kk * 32;
#pragma unroll
            for (int i = 0; i < 4; i++) {
                uint32_t ad = bufb + (m0w + i * 16 + arow) * 80 + acolb + kb;
                LDSM_X4(ah[i][0], ah[i][1], ah[i][2], ah[i][3], ad);
                LDSM_X4(al[i][0], al[i][1], al[i][2], al[i][3], ad + ARRB);
            }
            {
                uint32_t bd = bufb + 2 * ARRB + brow * 80 + bcolb + kb;
                uint32_t r0, r1, r2, r3;
                LDSM_X4(r0, r1, r2, r3, bd + n0w * 80);
                bh[0][0] = r0; bh[0][1] = r1; bh[1][0] = r2; bh[1][1] = r3;
                LDSM_X4(r0, r1, r2, r3, bd + (n0w + 16) * 80);
                bh[2][0] = r0; bh[2][1] = r1; bh[3][0] = r2; bh[3][1] = r3;
                LDSM_X4(r0, r1, r2, r3, bd + n0w * 80 + ARRB);
                bl[0][0] = r0; bl[0][1] = r1; bl[1][0] = r2; bl[1][1] = r3;
                LDSM_X4(r0, r1, r2, r3, bd + (n0w + 16) * 80 + ARRB);
                bl[2][0] = r0; bl[2][1] = r1; bl[3][0] = r2; bl[3][1] = r3;
            }
#pragma unroll
            for (int i = 0; i < 4; i++)
#pragma unroll
                for (int j = 0; j < 4; j++) {
                    MMA16816(acc[i][j], ah[i], bh[j]);
                    MMA16816(acc[i][j], ah[i], bl[j]);
                    MMA16816(acc[i][j], al[i], bh[j]);
                }
        }
    }
    __syncthreads();

    float* fsm = reinterpret_cast<float*>(dsm);
    const int r0w = m0w + (lane >> 2), c0w = n0w + (lane & 3) * 2;
#pragma unroll
    for (int i = 0; i < 4; i++)
#pragma unroll
        for (int j = 0; j < 4; j++) {
            int r = r0w + i * 16, cc = c0w + j * 8;
            fsm[r * EPIP + cc]           = acc[i][j][0];
            fsm[r * EPIP + cc + 1]       = acc[i][j][1];
            fsm[(r + 8) * EPIP + cc]     = acc[i][j][2];
            fsm[(r + 8) * EPIP + cc + 1] = acc[i][j][3];
        }
    __syncthreads();

    if (!qkv) {
#pragma unroll
        for (int l = 0; l < 64; l++) {
            int e = tid + l * 256;
            int r = e >> 7, cc = e & 127;
            C[(size_t)(m0 + r) * HID + n0 + cc] = fsm[r * EPIP + cc];
        }
    } else if (z < 2) {
        __nv_bfloat16* H = z ? Kh : Qh;
        __nv_bfloat16* L = z ? Kl : Ql;
#pragma unroll
        for (int l = 0; l < 32; l++) {
            int e = tid + l * 256;
            int r = e >> 6, c2 = (e & 63) * 2;
            float f0 = fsm[r * EPIP + c2], f1 = fsm[r * EPIP + c2 + 1];
            uint32_t hp = packbf2(f0, f1);
            uint32_t lp = packbf2(f0 - bflow(hp), f1 - bfhigh(hp));
            int n = n0 + c2;
            size_t o = ((size_t)(n >> 6) * S_LEN + m0 + r) * HDIM + (n & 63);
            *reinterpret_cast<uint32_t*>(H + o) = hp;
            *reinterpret_cast<uint32_t*>(L + o) = lp;
        }
    } else {
#pragma unroll
        for (int l = 0; l < 32; l++) {
            int e = tid + l * 256;
            int cc = e >> 6, rp = (e & 63) * 2;
            float f0 = fsm[rp * EPIP + cc], f1 = fsm[(rp + 1) * EPIP + cc];
            uint32_t hp = packbf2(f0, f1);
            uint32_t lp = packbf2(f0 - bflow(hp), f1 - bfhigh(hp));
            int n = n0 + cc;
            size_t o = ((size_t)(n >> 6) * HDIM + (n & 63)) * S_LEN + m0 + rp;
            *reinterpret_cast<uint32_t*>(Vh + o) = hp;
            *reinterpret_cast<uint32_t*>(Vl + o) = lp;
        }
    }
}

// ---------------- HMMA ring attention v4 ----------------
// 3-term QK (Kh+Kl) + 3-term PV; single-sync pipelines; cross-phase prefetch.
#define AQ      32
#define ROWB    4144
#define EP      1036
#define EBYTES  (AQ * ROWB)
#define ELOFF   2064
#define KPITCH  144
#define VPITCH  272
#define KTILE   (128 * KPITCH)
#define QPITCH  144
#define OFF_KBUF EBYTES
#define OFF_Q    (OFF_KBUF + 4 * KTILE)
#define OFF_DSH  (OFF_Q + 2 * 32 * QPITCH)
#define ASMEM    (OFF_DSH + 128)

__global__ __launch_bounds__(256) void attn2_k(
    const __nv_bfloat16* __restrict__ Qh, const __nv_bfloat16* __restrict__ Ql,
    const __nv_bfloat16* __restrict__ Kh, const __nv_bfloat16* __restrict__ Kl,
    const __nv_bfloat16* __restrict__ Vh, const __nv_bfloat16* __restrict__ Vl,
    __nv_bfloat16* __restrict__ Oh, __nv_bfloat16* __restrict__ Ol)
{
    extern __shared__ char smraw[];
    float* dsh = reinterpret_cast<float*>(smraw + OFF_DSH);
    const uint32_t sb = smem_u32(smraw);

    const int tid = threadIdx.x, wid = tid >> 5, lane = tid & 31;
    const int g = lane >> 2, tg = lane & 3;
    const int h = blockIdx.y, q0 = blockIdx.x * AQ;

    auto stageK = [&](int blk, int c, int b) {
        const uint32_t dst = sb + OFF_KBUF + b * 2 * KTILE;
        const size_t base = ((size_t)h * S_LEN + blk * 1024 + c * 128) * HDIM;
#pragma unroll
        for (int i = 0; i < 4; i++) {
            int e = tid + i * 256;
            int r = e >> 3, q = e & 7;
            CP_ASYNC16(dst + r * KPITCH + q * 16, Kh + base + (size_t)r * HDIM + q * 8);
            CP_ASYNC16(dst + KTILE + r * KPITCH + q * 16, Kl + base + (size_t)r * HDIM + q * 8);
        }
    };
    auto stageV = [&](int blk, int c, int b) {
        const uint32_t dst = sb + OFF_KBUF + b * 2 * KTILE;
        const size_t base = (size_t)h * HDIM * S_LEN + blk * 1024 + c * 128;
#pragma unroll
        for (int i = 0; i < 4; i++) {
            int e = tid + i * 256;
            int r = e >> 4, q = e & 15;
            CP_ASYNC16(dst + r * VPITCH + q * 16, Vh + base + (size_t)r * S_LEN + q * 8);
            CP_ASYNC16(dst + KTILE + r * VPITCH + q * 16, Vl + base + (size_t)r * S_LEN + q * 8);
        }
    };

    if (tid < 32) dsh[tid] = 0.f;
    {
        int r = tid >> 3, q = tid & 7;
        const size_t go = ((size_t)h * S_LEN + q0 + r) * HDIM + q * 8;
        CP_ASYNC16(sb + OFF_Q + r * QPITCH + q * 16, Qh + go);
        CP_ASYNC16(sb + OFF_Q + 32 * QPITCH + r * QPITCH + q * 16, Ql + go);
    }
    CP_COMMIT();
    stageK(0, 0, 0); CP_COMMIT();    // overlap K prefetch with Q wait
    CP_WAIT1();                      // waits the Q group only
    __syncthreads();

    uint32_t qfh[2][4][4], qfl[2][4][4];
    {
        int rA = lane & 15, cb = (lane >> 4) * 16;
#pragma unroll
        for (int mt = 0; mt < 2; mt++)
#pragma unroll
            for (int kt = 0; kt < 4; kt++) {
                uint32_t a = sb + OFF_Q + (mt * 16 + rA) * QPITCH + kt * 32 + cb;
                LDSM_X4(qfh[mt][kt][0], qfh[mt][kt][1], qfh[mt][kt][2], qfh[mt][kt][3], a);
                LDSM_X4(qfl[mt][kt][0], qfl[mt][kt][1], qfl[mt][kt][2], qfl[mt][kt][3],
                        a + 32 * QPITCH);
            }
    }

    float num[2][4];
#pragma unroll
    for (int n = 0; n < 2; n++)
#pragma unroll
        for (int r = 0; r < 4; r++) num[n][r] = 0.f;

    const int mtv = wid >> 2, np = wid & 3;

    for (int blk = 0; blk < NBLK; blk++) {
        // ================= QK^T (3-term, 1 sync/chunk) =================
        for (int c = 0; c < 8; c++) {
            CP_WAIT0();
            __syncthreads();
            if (c < 7) { stageK(blk, c + 1, (c + 1) & 1); CP_COMMIT(); }
            else       { stageV(blk, 0, 0); CP_COMMIT(); }   // V prefetch overlaps QK(7)+softmax

            const uint32_t kb = sb + OFF_KBUF + (c & 1) * 2 * KTILE;
            const int rB = wid * 16 + ((lane >> 4) & 1) * 8 + (lane & 7);
            const int cB = ((lane >> 3) & 1) * 16;

            float acc[2][2][4];
#pragma unroll
            for (int mt = 0; mt < 2; mt++)
#pragma unroll
                for (int nt = 0; nt < 2; nt++)
#pragma unroll
                    for (int r = 0; r < 4; r++) acc[mt][nt][r] = 0.f;

#pragma unroll
            for (int kt = 0; kt < 4; kt++) {
                uint32_t bh[4], bl[4];
                uint32_t ad = kb + rB * KPITCH + kt * 32 + cB;
                LDSM_X4(bh[0], bh[1], bh[2], bh[3], ad);
                LDSM_X4(bl[0], bl[1], bl[2], bl[3], ad + KTILE);
#pragma unroll
                for (int mt = 0; mt < 2; mt++)
#pragma unroll
                    for (int nt = 0; nt < 2; nt++) {
                        MMA16816(acc[mt][nt], qfh[mt][kt], &bh[nt * 2]);
                        MMA16816(acc[mt][nt], qfh[mt][kt], &bl[nt * 2]);
                        MMA16816(acc[mt][nt], qfl[mt][kt], &bh[nt * 2]);
                    }
            }
            uint32_t* ep = reinterpret_cast<uint32_t*>(smraw);
#pragma unroll
            for (int mt = 0; mt < 2; mt++)
#pragma unroll
                for (int nt = 0; nt < 2; nt++) {
                    int row = mt * 16 + g;
                    int col = c * 128 + wid * 16 + nt * 8 + tg * 2;
                    uint2 p0 = make_uint2(packsc(acc[mt][nt][0] * 0.125f),
                                          packsc(acc[mt][nt][1] * 0.125f));
                    uint2 p1 = make_uint2(packsc(acc[mt][nt][2] * 0.125f),
                                          packsc(acc[mt][nt][3] * 0.125f));
                    *reinterpret_cast<uint2*>(ep + row * EP + col) = p0;
                    *reinterpret_cast<uint2*>(ep + (row + 8) * EP + col) = p1;
                }
        }
        __syncthreads();   // all scores visible; V(0) still in flight

        // ============ softmax (overlaps V(0) cp.async) ============
#pragma unroll
        for (int rr = 0; rr < 4; rr++) {
            const int row = wid * 4 + rr;
            char* rowp = smraw + row * ROWB;
            uint4 pk[8];
            float m = -1e30f;
#pragma unroll
            for (int i = 0; i < 8; i++) {
                pk[i] = reinterpret_cast<uint4*>(rowp)[lane + 32 * i];
                float s0 = bflow(pk[i].x) + bfhigh(pk[i].x);
                float s1 = bflow(pk[i].y) + bfhigh(pk[i].y);
                float s2 = bflow(pk[i].z) + bfhigh(pk[i].z);
                float s3 = bflow(pk[i].w) + bfhigh(pk[i].w);
                m = fmaxf(m, fmaxf(fmaxf(s0, s1), fmaxf(s2, s3)));
            }
#pragma unroll
            for (int off = 16; off >= 1; off >>= 1)
                m = fmaxf(m, __shfl_xor_sync(0xffffffffu, m, off));
            const float mb = m * 1.4426950408889634f;
            float den = 0.f;
#pragma unroll
            for (int i = 0; i < 8; i++) {
                float e0 = fex2(fmaf(bflow(pk[i].x) + bfhigh(pk[i].x), 1.4426950408889634f, -mb));
                float e1 = fex2(fmaf(bflow(pk[i].y) + bfhigh(pk[i].y), 1.4426950408889634f, -mb));
                float e2 = fex2(fmaf(bflow(pk[i].z) + bfhigh(pk[i].z), 1.4426950408889634f, -mb));
                float e3 = fex2(fmaf(bflow(pk[i].w) + bfhigh(pk[i].w), 1.4426950408889634f, -mb));
                den += (e0 + e1) + (e2 + e3);
                uint32_t hx = packbf2(e0, e1), hy = packbf2(e2, e3);
                uint32_t lx = packbf2(e0 - bflow(hx), e1 - bfhigh(hx));
                uint32_t ly = packbf2(e2 - bflow(hy), e3 - bfhigh(hy));
                reinterpret_cast<uint2*>(rowp)[lane + 32 * i] = make_uint2(hx, hy);
                reinterpret_cast<uint2*>(rowp + ELOFF)[lane + 32 * i] = make_uint2(lx, ly);
            }
#pragma unroll
            for (int off = 16; off >= 1; off >>= 1)
                den += __shfl_xor_sync(0xffffffffu, den, off);
            if (lane == 0) dsh[row] += den;
        }

        // ================= PV (3-term, 1 sync/chunk) =================
        for (int c = 0; c < 8; c++) {
            CP_WAIT0();
            __syncthreads();   // first iter: doubles as post-softmax barrier
            if (c < 7)          { stageV(blk, c + 1, (c + 1) & 1); CP_COMMIT(); }
            else if (blk < 3)   { stageK(blk + 1, 0, 0); CP_COMMIT(); }  // next-K overlaps PV(7)

            const uint32_t vb = sb + OFF_KBUF + (c & 1) * 2 * KTILE;
            const int rB = np * 16 + ((lane >> 4) & 1) * 8 + (lane & 7);
            const int cB = ((lane >> 3) & 1) * 16;
            const uint32_t ebase = sb + (mtv * 16 + (lane & 15)) * ROWB
                                 + (lane >> 4) * 16 + c * 256;

#pragma unroll
            for (int u = 0; u < 8; u++) {
                uint32_t aH[4], aL[4];
                LDSM_X4(aH[0], aH[1], aH[2], aH[3], ebase + u * 32);
                LDSM_X4(aL[0], aL[1], aL[2], aL[3], ebase + u * 32 + ELOFF);
                uint32_t bh[4], bl[4];
                uint32_t ad = vb + rB * VPITCH + u * 32 + cB;
                LDSM_X4(bh[0], bh[1], bh[2], bh[3], ad);
                LDSM_X4(bl[0], bl[1], bl[2], bl[3], ad + KTILE);
                MMA16816(num[0], aH, &bh[0]);
                MMA16816(num[0], aH, &bl[0]);
                MMA16816(num[0], aL, &bh[0]);
                MMA16816(num[1], aH, &bh[2]);
                MMA16816(num[1], aH, &bl[2]);
                MMA16816(num[1], aL, &bh[2]);
            }
        }
    }

    {
        const int r0 = mtv * 16 + g;
        const float id0 = 1.0f / dsh[r0];
        const float id1 = 1.0f / dsh[r0 + 8];
#pragma unroll
        for (int nt = 0; nt < 2; nt++) {
            const int col = h * HDIM + np * 16 + nt * 8 + tg * 2;
            float o0 = num[nt][0] * id0, o1 = num[nt][1] * id0;
            float o2 = num[nt][2] * id1, o3 = num[nt][3] * id1;
            uint32_t hp0 = packbf2(o0, o1);
            uint32_t lp0 = packbf2(o0 - bflow(hp0), o1 - bfhigh(hp0));
            uint32_t hp1 = packbf2(o2, o3);
            uint32_t lp1 = packbf2(o2 - bflow(hp1), o3 - bfhigh(hp1));
            size_t a0 = (size_t)(q0 + r0) * HID + col;
            size_t a1 = (size_t)(q0 + r0 + 8) * HID + col;
            *reinterpret_cast<uint32_t*>(Oh + a0) = hp0;
            *reinterpret_cast<uint32_t*>(Ol + a0) = lp0;
            *reinterpret_cast<uint32_t*>(Oh + a1) = hp1;
            *reinterpret_cast<uint32_t*>(Ol + a1) = lp1;
        }
    }
}

// ---------------- launch ----------------
extern "C" void kernel_launch(void* const* d_in, const int* in_sizes, int n_in,
                              void* d_out, int out_size)
{
    const float* x = (const float*)d_in[0];
    float* out = (float*)d_out;

    __nv_bfloat16 *Xh, *Xl, *Qh, *Ql, *Kh, *Kl, *Vh, *Vl, *Ah, *Al, *Wh, *Wl;
    cudaGetSymbolAddress((void**)&Xh, g_Xh); cudaGetSymbolAddress((void**)&Xl, g_Xl);
    cudaGetSymbolAddress((void**)&Qh, g_Qh); cudaGetSymbolAddress((void**)&Ql, g_Ql);
    cudaGetSymbolAddress((void**)&Kh, g_Kh); cudaGetSymbolAddress((void**)&Kl, g_Kl);
    cudaGetSymbolAddress((void**)&Vh, g_Vh); cudaGetSymbolAddress((void**)&Vl, g_Vl);
    cudaGetSymbolAddress((void**)&Ah, g_Ah); cudaGetSymbolAddress((void**)&Al, g_Al);
    cudaGetSymbolAddress((void**)&Wh, g_Wh); cudaGetSymbolAddress((void**)&Wl, g_Wl);

    const int gemm_smem = 2 * BUFB;
    cudaFuncSetAttribute(gemmmma_k, cudaFuncAttributeMaxDynamicSharedMemorySize, gemm_smem);
    cudaFuncSetAttribute(attn2_k, cudaFuncAttributeMaxDynamicSharedMemorySize, ASMEM);

    convhl_k<<<(S_LEN * HID) / 1024, 256>>>(x, Xh, Xl);
    convwt_k<<<dim3(HID / 32, HID / 32, 4), 256>>>((const float*)d_in[1], (const float*)d_in[2],
                                                   (const float*)d_in[3], (const float*)d_in[4],
                                                   Wh, Wl);

    // merged Q/K/V projection: one launch, 768 CTAs
    gemmmma_k<<<dim3(HID / 128, S_LEN / 128, 3), 256, gemm_smem>>>(
        Xh, Xl, Wh, Wl, nullptr, Qh, Ql, Kh, Kl, Vh, Vl, 1);

    dim3 ag(S_LEN / AQ, HEADS);
    attn2_k<<<ag, 256, ASMEM>>>(Qh, Ql, Kh, Kl, Vh, Vl, Ah, Al);

    gemmmma_k<<<dim3(HID / 128, S_LEN / 128, 1), 256, gemm_smem>>>(
        Ah, Al, Wh + 3 * (size_t)HID * HID, Wl + 3 * (size_t)HID * HID,
        out, nullptr, nullptr, nullptr, nullptr, nullptr, nullptr, 0);
}

// round 10
// speedup vs baseline: 1.2651x; 1.2651x over previous
#include <cuda_runtime.h>
#include <cuda_bf16.h>
#include <cuda_fp16.h>
#include <cstdint>

#define S_LEN 4096
#define HID   1024
#define HEADS 16
#define HDIM  64
#define NBLK  4

__device__ __nv_bfloat16 g_Xh[S_LEN * HID], g_Xl[S_LEN * HID];
__device__ __nv_bfloat16 g_Ah[S_LEN * HID], g_Al[S_LEN * HID];   // attn out [s][hid]
__device__ __nv_bfloat16 g_Wh[4][HID * HID], g_Wl[4][HID * HID];
__device__ __half g_Qh2[S_LEN * HID], g_Ql2[S_LEN * HID];        // [h][s][d] fp16 hi/lo
__device__ __half g_K2[S_LEN * HID];                              // [h][s][d] fp16
__device__ __half g_V2[S_LEN * HID];                              // [h][d][s] fp16

__device__ __forceinline__ uint32_t smem_u32(const void* p) {
    uint32_t a;
    asm("{ .reg .u64 t; cvta.to.shared.u64 t, %1; cvt.u32.u64 %0, t; }" : "=r"(a) : "l"(p));
    return a;
}
#define CP_ASYNC16(dst, src) \
    asm volatile("cp.async.cg.shared.global [%0], [%1], 16;" :: "r"(dst), "l"(src))
#define CP_COMMIT() asm volatile("cp.async.commit_group;" ::: "memory")
#define CP_WAIT0()  asm volatile("cp.async.wait_group 0;" ::: "memory")
#define CP_WAIT1()  asm volatile("cp.async.wait_group 1;" ::: "memory")
#define LDSM_X4(r0, r1, r2, r3, addr) \
    asm volatile("ldmatrix.sync.aligned.m8n8.x4.shared.b16 {%0,%1,%2,%3}, [%4];" \
                 : "=r"(r0), "=r"(r1), "=r"(r2), "=r"(r3) : "r"(addr))
#define MMA16816(d, a, b) \
    asm volatile("mma.sync.aligned.m16n8k16.row.col.f32.bf16.bf16.f32 " \
                 "{%0,%1,%2,%3}, {%4,%5,%6,%7}, {%8,%9}, {%0,%1,%2,%3};" \
                 : "+f"((d)[0]), "+f"((d)[1]), "+f"((d)[2]), "+f"((d)[3]) \
                 : "r"((a)[0]), "r"((a)[1]), "r"((a)[2]), "r"((a)[3]), \
                   "r"((b)[0]), "r"((b)[1]))
#define MMAH16816(d, a, b) \
    asm volatile("mma.sync.aligned.m16n8k16.row.col.f32.f16.f16.f32 " \
                 "{%0,%1,%2,%3}, {%4,%5,%6,%7}, {%8,%9}, {%0,%1,%2,%3};" \
                 : "+f"((d)[0]), "+f"((d)[1]), "+f"((d)[2]), "+f"((d)[3]) \
                 : "r"((a)[0]), "r"((a)[1]), "r"((a)[2]), "r"((a)[3]), \
                   "r"((b)[0]), "r"((b)[1]))

__device__ __forceinline__ uint32_t packbf2(float a, float b) {
    uint32_t r;
    asm("cvt.rn.bf16x2.f32 %0, %1, %2;" : "=r"(r) : "f"(b), "f"(a));
    return r;
}
__device__ __forceinline__ uint32_t packh2(float a, float b) {
    uint32_t r;
    asm("cvt.rn.f16x2.f32 %0, %1, %2;" : "=r"(r) : "f"(b), "f"(a));
    return r;
}
__device__ __forceinline__ float bflow(uint32_t p)  { return __uint_as_float(p << 16); }
__device__ __forceinline__ float bfhigh(uint32_t p) { return __uint_as_float(p & 0xffff0000u); }
__device__ __forceinline__ uint32_t packsc(float s) {
    float hf = __bfloat162float(__float2bfloat16(s));
    return packbf2(s, s - hf);
}
__device__ __forceinline__ float fex2(float x) {
    float e;
    asm("ex2.approx.f32 %0, %1;" : "=f"(e) : "f"(x));
    return e;
}

// ---------------- conversions ----------------
__global__ __launch_bounds__(256) void convhl_k(const float* __restrict__ X,
                                                __nv_bfloat16* __restrict__ H,
                                                __nv_bfloat16* __restrict__ L)
{
    int i = (blockIdx.x * 256 + threadIdx.x) * 4;
    float4 v = *reinterpret_cast<const float4*>(X + i);
    float f[4] = {v.x, v.y, v.z, v.w};
    __nv_bfloat16 h[4], l[4];
#pragma unroll
    for (int j = 0; j < 4; j++) {
        h[j] = __float2bfloat16(f[j]);
        l[j] = __float2bfloat16(f[j] - __bfloat162float(h[j]));
    }
    *reinterpret_cast<uint2*>(H + i) = *reinterpret_cast<uint2*>(h);
    *reinterpret_cast<uint2*>(L + i) = *reinterpret_cast<uint2*>(l);
}

__global__ __launch_bounds__(256) void convwt_k(const float* __restrict__ w0,
                                                const float* __restrict__ w1,
                                                const float* __restrict__ w2,
                                                const float* __restrict__ w3,
                                                __nv_bfloat16* __restrict__ HtB,
                                                __nv_bfloat16* __restrict__ LtB)
{
    __shared__ float t[32][33];
    const int z = blockIdx.z;
    const float* W = (z == 0) ? w0 : (z == 1) ? w1 : (z == 2) ? w2 : w3;
    __nv_bfloat16* Ht = HtB + (size_t)z * HID * HID;
    __nv_bfloat16* Lt = LtB + (size_t)z * HID * HID;
    int n0 = blockIdx.x * 32, k0 = blockIdx.y * 32;
    int tx = threadIdx.x & 31, ty = threadIdx.x >> 5;
#pragma unroll
    for (int s = 0; s < 32; s += 8)
        t[ty + s][tx] = W[(size_t)(k0 + ty + s) * HID + n0 + tx];
    __syncthreads();
#pragma unroll
    for (int s = 0; s < 32; s += 8) {
        float v = t[tx][ty + s];
        __nv_bfloat16 h = __float2bfloat16(v);
        __nv_bfloat16 l = __float2bfloat16(v - __bfloat162float(h));
        size_t o = (size_t)(n0 + ty + s) * HID + k0 + tx;
        Ht[o] = h; Lt[o] = l;
    }
}

// ---------------- HMMA 3-term GEMM ----------------
// qkv=1: z=0 -> Q fp16 h/l [h][s][d]; z=1 -> K fp16 [h][s][d]; z=2 -> V fp16 [h][d][s]
// qkv=0: fp32 C [m][HID]
#define GKC  32
#define GNC  (HID / GKC)
#define ARRB (128 * 80)
#define BUFB (4 * ARRB)
#define EPIP 129

__global__ __launch_bounds__(256) void gemmmma_k(const __nv_bfloat16* __restrict__ Ap,
                                                 const __nv_bfloat16* __restrict__ Alp,
                                                 const __nv_bfloat16* __restrict__ WhB,
                                                 const __nv_bfloat16* __restrict__ WlB,
                                                 float* __restrict__ C,
                                                 __half* __restrict__ Qh,
                                                 __half* __restrict__ Ql,
                                                 __half* __restrict__ Kg,
                                                 __half* __restrict__ Vg,
                                                 int qkv)
{
    extern __shared__ char dsm[];
    const uint32_t sbase = smem_u32(dsm);
    const int tid = threadIdx.x, wid = tid >> 5, lane = tid & 31;
    const int m0 = blockIdx.y * 128, n0 = blockIdx.x * 128;
    const int m0w = (wid & 1) * 64, n0w = (wid >> 1) * 32;
    const int z = qkv ? blockIdx.z : 0;
    const __nv_bfloat16* Bp  = WhB + (size_t)z * HID * HID;
    const __nv_bfloat16* Blp = WlB + (size_t)z * HID * HID;

    float acc[4][4][4];
#pragma unroll
    for (int i = 0; i < 4; i++)
#pragma unroll
        for (int j = 0; j < 4; j++)
#pragma unroll
            for (int r = 0; r < 4; r++) acc[i][j][r] = 0.f;

    auto load_chunk = [&](int c, int b) {
        const int koff = c * GKC;
        const uint32_t dst0 = sbase + b * BUFB;
#pragma unroll
        for (int l = 0; l < 8; l++) {
            int e = tid + l * 256;
            int arr = e >> 9, r = (e >> 2) & 127, q = e & 3;
            const __nv_bfloat16* G = (arr == 0) ? Ap : (arr == 1) ? Alp
                                   : (arr == 2) ? Bp : Blp;
            int t0 = (arr < 2) ? m0 : n0;
            CP_ASYNC16(dst0 + arr * ARRB + r * 80 + q * 16,
                       G + (size_t)(t0 + r) * HID + koff + q * 8);
        }
    };

    load_chunk(0, 0);
    CP_COMMIT();

    const int arow = lane & 15, acolb = (lane >> 4) * 16;
    const int brow = ((lane >> 4) << 3) + (lane & 7);
    const int bcolb = ((lane >> 3) & 1) * 16;

    for (int c = 0; c < GNC; c++) {
        const int b = c & 1;
        CP_WAIT0();
        __syncthreads();
        if (c + 1 < GNC) { load_chunk(c + 1, (c + 1) & 1); CP_COMMIT(); }

        const uint32_t bufb = sbase + b * BUFB;
#pragma unroll
        for (int kk = 0; kk < 2; kk++) {
            uint32_t ah[4][4], al[4][4], bh[4][2], bl[4][2];
            const int kb = kk * 32;
#pragma unroll
            for (int i = 0; i < 4; i++) {
                uint32_t ad = bufb + (m0w + i * 16 + arow) * 80 + acolb + kb;
                LDSM_X4(ah[i][0], ah[i][1], ah[i][2], ah[i][3], ad);
                LDSM_X4(al[i][0], al[i][1], al[i][2], al[i][3], ad + ARRB);
            }
            {
                uint32_t bd = bufb + 2 * ARRB + brow * 80 + bcolb + kb;
                uint32_t r0, r1, r2, r3;
                LDSM_X4(r0, r1, r2, r3, bd + n0w * 80);
                bh[0][0] = r0; bh[0][1] = r1; bh[1][0] = r2; bh[1][1] = r3;
                LDSM_X4(r0, r1, r2, r3, bd + (n0w + 16) * 80);
                bh[2][0] = r0; bh[2][1] = r1; bh[3][0] = r2; bh[3][1] = r3;
                LDSM_X4(r0, r1, r2, r3, bd + n0w * 80 + ARRB);
                bl[0][0] = r0; bl[0][1] = r1; bl[1][0] = r2; bl[1][1] = r3;
                LDSM_X4(r0, r1, r2, r3, bd + (n0w + 16) * 80 + ARRB);
                bl[2][0] = r0; bl[2][1] = r1; bl[3][0] = r2; bl[3][1] = r3;
            }
#pragma unroll
            for (int i = 0; i < 4; i++)
#pragma unroll
                for (int j = 0; j < 4; j++) {
                    MMA16816(acc[i][j], ah[i], bh[j]);
                    MMA16816(acc[i][j], ah[i], bl[j]);
                    MMA16816(acc[i][j], al[i], bh[j]);
                }
        }
    }
    __syncthreads();

    float* fsm = reinterpret_cast<float*>(dsm);
    const int r0w = m0w + (lane >> 2), c0w = n0w + (lane & 3) * 2;
#pragma unroll
    for (int i = 0; i < 4; i++)
#pragma unroll
        for (int j = 0; j < 4; j++) {
            int r = r0w + i * 16, cc = c0w + j * 8;
            fsm[r * EPIP + cc]           = acc[i][j][0];
            fsm[r * EPIP + cc + 1]       = acc[i][j][1];
            fsm[(r + 8) * EPIP + cc]     = acc[i][j][2];
            fsm[(r + 8) * EPIP + cc + 1] = acc[i][j][3];
        }
    __syncthreads();

    if (!qkv) {
#pragma unroll
        for (int l = 0; l < 64; l++) {
            int e = tid + l * 256;
            int r = e >> 7, cc = e & 127;
            C[(size_t)(m0 + r) * HID + n0 + cc] = fsm[r * EPIP + cc];
        }
    } else if (z == 0) {
        // Q: fp16 hi/lo, [h][s][d]
#pragma unroll
        for (int l = 0; l < 32; l++) {
            int e = tid + l * 256;
            int r = e >> 6, c2 = (e & 63) * 2;
            float f0 = fsm[r * EPIP + c2], f1 = fsm[r * EPIP + c2 + 1];
            __half h0 = __float2half_rn(f0), h1 = __float2half_rn(f1);
            __half l0 = __float2half_rn(f0 - __half2float(h0));
            __half l1 = __float2half_rn(f1 - __half2float(h1));
            int n = n0 + c2;
            size_t o = ((size_t)(n >> 6) * S_LEN + m0 + r) * HDIM + (n & 63);
            *reinterpret_cast<__half2*>(Qh + o) = __halves2half2(h0, h1);
            *reinterpret_cast<__half2*>(Ql + o) = __halves2half2(l0, l1);
        }
    } else if (z == 1) {
        // K: fp16 single, [h][s][d]
#pragma unroll
        for (int l = 0; l < 32; l++) {
            int e = tid + l * 256;
            int r = e >> 6, c2 = (e & 63) * 2;
            float f0 = fsm[r * EPIP + c2], f1 = fsm[r * EPIP + c2 + 1];
            int n = n0 + c2;
            size_t o = ((size_t)(n >> 6) * S_LEN + m0 + r) * HDIM + (n & 63);
            *reinterpret_cast<__half2*>(Kg + o) =
                __halves2half2(__float2half_rn(f0), __float2half_rn(f1));
        }
    } else {
        // V: fp16 single, [h][d][s]
#pragma unroll
        for (int l = 0; l < 32; l++) {
            int e = tid + l * 256;
            int cc = e >> 6, rp = (e & 63) * 2;
            float f0 = fsm[rp * EPIP + cc], f1 = fsm[(rp + 1) * EPIP + cc];
            int n = n0 + cc;
            size_t o = ((size_t)(n >> 6) * HDIM + (n & 63)) * S_LEN + m0 + rp;
            *reinterpret_cast<__half2*>(Vg + o) =
                __halves2half2(__float2half_rn(f0), __float2half_rn(f1));
        }
    }
}

// ---------------- fp16 ring attention v5: AQ=16, 128 thr, 2 CTAs/SM ----------------
#define AQ      16
#define ROWB    4144
#define EP      1036
#define EBYTES  (AQ * ROWB)              // 66304
#define CPITCH  144
#define CTILE   (64 * CPITCH)            // 9216
#define QP2     144
#define OFF_KV  EBYTES
#define OFF_Q   (OFF_KV + 2 * CTILE)     // 84736
#define OFF_DSH (OFF_Q + 2 * AQ * QP2)   // 89344
#define ASMEM   (OFF_DSH + 64)           // 89408

__global__ __launch_bounds__(128) void attn3_k(
    const __half* __restrict__ Qh, const __half* __restrict__ Ql,
    const __half* __restrict__ Kg, const __half* __restrict__ Vg,
    __nv_bfloat16* __restrict__ Oh, __nv_bfloat16* __restrict__ Ol)
{
    extern __shared__ char smraw[];
    float* dsh = reinterpret_cast<float*>(smraw + OFF_DSH);
    const uint32_t sb = smem_u32(smraw);

    const int tid = threadIdx.x, wid = tid >> 5, lane = tid & 31;
    const int g = lane >> 2, tg = lane & 3;
    const int h = blockIdx.y, q0 = blockIdx.x * AQ;

    auto stageK = [&](int blk, int c, int b) {
        const uint32_t dst = sb + OFF_KV + b * CTILE;
        const __half* src = Kg + ((size_t)h * S_LEN + blk * 1024 + c * 64) * HDIM;
#pragma unroll
        for (int i = 0; i < 4; i++) {
            int e = tid + i * 128;
            int r = e >> 3, q = e & 7;
            CP_ASYNC16(dst + r * CPITCH + q * 16, src + (size_t)r * HDIM + q * 8);
        }
    };
    auto stageV = [&](int blk, int c, int b) {
        const uint32_t dst = sb + OFF_KV + b * CTILE;
        const __half* src = Vg + (size_t)h * HDIM * S_LEN + blk * 1024 + c * 64;
#pragma unroll
        for (int i = 0; i < 4; i++) {
            int e = tid + i * 128;
            int r = e >> 3, q = e & 7;
            CP_ASYNC16(dst + r * CPITCH + q * 16, src + (size_t)r * S_LEN + q * 8);
        }
    };

    if (tid < AQ) dsh[tid] = 0.f;
    {
        int r = tid >> 3, q = tid & 7;
        const size_t go = ((size_t)h * S_LEN + q0 + r) * HDIM + q * 8;
        CP_ASYNC16(sb + OFF_Q + r * QP2 + q * 16, Qh + go);
        CP_ASYNC16(sb + OFF_Q + AQ * QP2 + r * QP2 + q * 16, Ql + go);
    }
    CP_COMMIT();
    stageK(0, 0, 0); CP_COMMIT();
    CP_WAIT1();                       // Q group done; K(0) in flight
    __syncthreads();

    uint32_t qfh[4][4], qfl[4][4];
    {
        const uint32_t a0 = sb + OFF_Q + (lane & 15) * QP2 + (lane >> 4) * 16;
#pragma unroll
        for (int kt = 0; kt < 4; kt++) {
            LDSM_X4(qfh[kt][0], qfh[kt][1], qfh[kt][2], qfh[kt][3], a0 + kt * 32);
            LDSM_X4(qfl[kt][0], qfl[kt][1], qfl[kt][2], qfl[kt][3],
                    a0 + kt * 32 + AQ * QP2);
        }
    }

    float num[2][4];
#pragma unroll
    for (int n = 0; n < 2; n++)
#pragma unroll
        for (int r = 0; r < 4; r++) num[n][r] = 0.f;

    const int rB = wid * 16 + ((lane >> 4) & 1) * 8 + (lane & 7);
    const int cB = ((lane >> 3) & 1) * 16;

    for (int blk = 0; blk < NBLK; blk++) {
        // ============ QK^T: 2-term fp16, 16 chunks of 64 keys ============
        for (int c = 0; c < 16; c++) {
            CP_WAIT0();
            __syncthreads();
            if (c < 15) { stageK(blk, c + 1, (c + 1) & 1); CP_COMMIT(); }
            else        { stageV(blk, 0, 0); CP_COMMIT(); }

            const uint32_t kb = sb + OFF_KV + (c & 1) * CTILE;
            float acc[2][4];
#pragma unroll
            for (int nt = 0; nt < 2; nt++)
#pragma unroll
                for (int r = 0; r < 4; r++) acc[nt][r] = 0.f;

#pragma unroll
            for (int kt = 0; kt < 4; kt++) {
                uint32_t bh[4];
                LDSM_X4(bh[0], bh[1], bh[2], bh[3], kb + rB * CPITCH + kt * 32 + cB);
                MMAH16816(acc[0], qfh[kt], &bh[0]);
                MMAH16816(acc[0], qfl[kt], &bh[0]);
                MMAH16816(acc[1], qfh[kt], &bh[2]);
                MMAH16816(acc[1], qfl[kt], &bh[2]);
            }
            uint32_t* ep = reinterpret_cast<uint32_t*>(smraw);
#pragma unroll
            for (int nt = 0; nt < 2; nt++) {
                int col = c * 64 + wid * 16 + nt * 8 + tg * 2;
                *reinterpret_cast<uint2*>(ep + g * EP + col) =
                    make_uint2(packsc(acc[nt][0] * 0.125f), packsc(acc[nt][1] * 0.125f));
                *reinterpret_cast<uint2*>(ep + (g + 8) * EP + col) =
                    make_uint2(packsc(acc[nt][2] * 0.125f), packsc(acc[nt][3] * 0.125f));
            }
        }
        __syncthreads();   // scores visible; V(0) in flight

        // ============ softmax: block-local max, E -> fp16 plane ============
#pragma unroll
        for (int rr = 0; rr < 4; rr++) {
            const int row = wid * 4 + rr;
            char* rowp = smraw + row * ROWB;
            uint4 pk[8];
            float m = -1e30f;
#pragma unroll
            for (int i = 0; i < 8; i++) {
                pk[i] = reinterpret_cast<uint4*>(rowp)[lane + 32 * i];
                float s0 = bflow(pk[i].x) + bfhigh(pk[i].x);
                float s1 = bflow(pk[i].y) + bfhigh(pk[i].y);
                float s2 = bflow(pk[i].z) + bfhigh(pk[i].z);
                float s3 = bflow(pk[i].w) + bfhigh(pk[i].w);
                m = fmaxf(m, fmaxf(fmaxf(s0, s1), fmaxf(s2, s3)));
            }
#pragma unroll
            for (int off = 16; off >= 1; off >>= 1)
                m = fmaxf(m, __shfl_xor_sync(0xffffffffu, m, off));
            const float mb = m * 1.4426950408889634f;
            float den = 0.f;
#pragma unroll
            for (int i = 0; i < 8; i++) {
                float e0 = fex2(fmaf(bflow(pk[i].x) + bfhigh(pk[i].x), 1.4426950408889634f, -mb));
                float e1 = fex2(fmaf(bflow(pk[i].y) + bfhigh(pk[i].y), 1.4426950408889634f, -mb));
                float e2 = fex2(fmaf(bflow(pk[i].z) + bfhigh(pk[i].z), 1.4426950408889634f, -mb));
                float e3 = fex2(fmaf(bflow(pk[i].w) + bfhigh(pk[i].w), 1.4426950408889634f, -mb));
                den += (e0 + e1) + (e2 + e3);
                reinterpret_cast<uint2*>(rowp)[lane + 32 * i] =
                    make_uint2(packh2(e0, e1), packh2(e2, e3));
            }
#pragma unroll
            for (int off = 16; off >= 1; off >>= 1)
                den += __shfl_xor_sync(0xffffffffu, den, off);
            if (lane == 0) dsh[row] += den;
        }

        // ============ PV: 1-term fp16 (E x V), 16 chunks ============
        for (int c = 0; c < 16; c++) {
            CP_WAIT0();
            __syncthreads();   // first iter doubles as post-softmax barrier
            if (c < 15)        { stageV(blk, c + 1, (c + 1) & 1); CP_COMMIT(); }
            else if (blk < 3)  { stageK(blk + 1, 0, 0); CP_COMMIT(); }

            const uint32_t vb = sb + OFF_KV + (c & 1) * CTILE;
            const uint32_t ebase = sb + (lane & 15) * ROWB + (lane >> 4) * 16 + c * 128;

#pragma unroll
            for (int u = 0; u < 4; u++) {
                uint32_t aH[4], bh[4];
                LDSM_X4(aH[0], aH[1], aH[2], aH[3], ebase + u * 32);
                LDSM_X4(bh[0], bh[1], bh[2], bh[3], vb + rB * CPITCH + u * 32 + cB);
                MMAH16816(num[0], aH, &bh[0]);
                MMAH16816(num[1], aH, &bh[2]);
            }
        }
    }

    // ---- epilogue: normalize, bf16 hi/lo out ----
    {
        const float id0 = 1.0f / dsh[g];
        const float id1 = 1.0f / dsh[g + 8];
#pragma unroll
        for (int nt = 0; nt < 2; nt++) {
            const int col = h * HDIM + wid * 16 + nt * 8 + tg * 2;
            float o0 = num[nt][0] * id0, o1 = num[nt][1] * id0;
            float o2 = num[nt][2] * id1, o3 = num[nt][3] * id1;
            uint32_t hp0 = packbf2(o0, o1);
            uint32_t lp0 = packbf2(o0 - bflow(hp0), o1 - bfhigh(hp0));
            uint32_t hp1 = packbf2(o2, o3);
            uint32_t lp1 = packbf2(o2 - bflow(hp1), o3 - bfhigh(hp1));
            size_t a0 = (size_t)(q0 + g) * HID + col;
            size_t a1 = (size_t)(q0 + g + 8) * HID + col;
            *reinterpret_cast<uint32_t*>(Oh + a0) = hp0;
            *reinterpret_cast<uint32_t*>(Ol + a0) = lp0;
            *reinterpret_cast<uint32_t*>(Oh + a1) = hp1;
            *reinterpret_cast<uint32_t*>(Ol + a1) = lp1;
        }
    }
}

// ---------------- launch ----------------
extern "C" void kernel_launch(void* const* d_in, const int* in_sizes, int n_in,
                              void* d_out, int out_size)
{
    const float* x = (const float*)d_in[0];
    float* out = (float*)d_out;

    __nv_bfloat16 *Xh, *Xl, *Ah, *Al, *Wh, *Wl;
    __half *Qh, *Ql, *Kg, *Vg;
    cudaGetSymbolAddress((void**)&Xh, g_Xh); cudaGetSymbolAddress((void**)&Xl, g_Xl);
    cudaGetSymbolAddress((void**)&Ah, g_Ah); cudaGetSymbolAddress((void**)&Al, g_Al);
    cudaGetSymbolAddress((void**)&Wh, g_Wh); cudaGetSymbolAddress((void**)&Wl, g_Wl);
    cudaGetSymbolAddress((void**)&Qh, g_Qh2); cudaGetSymbolAddress((void**)&Ql, g_Ql2);
    cudaGetSymbolAddress((void**)&Kg, g_K2);  cudaGetSymbolAddress((void**)&Vg, g_V2);

    const int gemm_smem = 2 * BUFB;
    cudaFuncSetAttribute(gemmmma_k, cudaFuncAttributeMaxDynamicSharedMemorySize, gemm_smem);
    cudaFuncSetAttribute(attn3_k, cudaFuncAttributeMaxDynamicSharedMemorySize, ASMEM);

    convhl_k<<<(S_LEN * HID) / 1024, 256>>>(x, Xh, Xl);
    convwt_k<<<dim3(HID / 32, HID / 32, 4), 256>>>((const float*)d_in[1], (const float*)d_in[2],
                                                   (const float*)d_in[3], (const float*)d_in[4],
                                                   Wh, Wl);

    // merged Q/K/V projection
    gemmmma_k<<<dim3(HID / 128, S_LEN / 128, 3), 256, gemm_smem>>>(
        Xh, Xl, Wh, Wl, nullptr, Qh, Ql, Kg, Vg, 1);

    dim3 ag(S_LEN / AQ, HEADS);
    attn3_k<<<ag, 128, ASMEM>>>(Qh, Ql, Kg, Vg, Ah, Al);

    gemmmma_k<<<dim3(HID / 128, S_LEN / 128, 1), 256, gemm_smem>>>(
        Ah, Al, Wh + 3 * (size_t)HID * HID, Wl + 3 * (size_t)HID * HID,
        out, nullptr, nullptr, nullptr, nullptr, 0);
}

// round 11
// speedup vs baseline: 1.5840x; 1.2521x over previous
#include <cuda_runtime.h>
#include <cuda_bf16.h>
#include <cuda_fp16.h>
#include <cstdint>

#define S_LEN 4096
#define HID   1024
#define HEADS 16
#define HDIM  64
#define NBLK  4

__device__ __nv_bfloat16 g_Xh[S_LEN * HID], g_Xl[S_LEN * HID];
__device__ __nv_bfloat16 g_Ah[S_LEN * HID], g_Al[S_LEN * HID];   // attn out [s][hid]
__device__ __nv_bfloat16 g_Wh[4][HID * HID], g_Wl[4][HID * HID];
__device__ __half g_Qh2[S_LEN * HID], g_Ql2[S_LEN * HID];        // [h][s][d] fp16 hi/lo
__device__ __half g_K2[S_LEN * HID];                              // [h][s][d] fp16
__device__ __half g_V2[S_LEN * HID];                              // [h][d][s] fp16

__device__ __forceinline__ uint32_t smem_u32(const void* p) {
    uint32_t a;
    asm("{ .reg .u64 t; cvta.to.shared.u64 t, %1; cvt.u32.u64 %0, t; }" : "=r"(a) : "l"(p));
    return a;
}
#define CP_ASYNC16(dst, src) \
    asm volatile("cp.async.cg.shared.global [%0], [%1], 16;" :: "r"(dst), "l"(src))
#define CP_COMMIT() asm volatile("cp.async.commit_group;" ::: "memory")
#define CP_WAIT0()  asm volatile("cp.async.wait_group 0;" ::: "memory")
#define CP_WAIT1()  asm volatile("cp.async.wait_group 1;" ::: "memory")
#define CP_WAIT3()  asm volatile("cp.async.wait_group 3;" ::: "memory")
#define LDSM_X4(r0, r1, r2, r3, addr) \
    asm volatile("ldmatrix.sync.aligned.m8n8.x4.shared.b16 {%0,%1,%2,%3}, [%4];" \
                 : "=r"(r0), "=r"(r1), "=r"(r2), "=r"(r3) : "r"(addr))
#define MMA16816(d, a, b) \
    asm volatile("mma.sync.aligned.m16n8k16.row.col.f32.bf16.bf16.f32 " \
                 "{%0,%1,%2,%3}, {%4,%5,%6,%7}, {%8,%9}, {%0,%1,%2,%3};" \
                 : "+f"((d)[0]), "+f"((d)[1]), "+f"((d)[2]), "+f"((d)[3]) \
                 : "r"((a)[0]), "r"((a)[1]), "r"((a)[2]), "r"((a)[3]), \
                   "r"((b)[0]), "r"((b)[1]))
#define MMAH16816(d, a, b) \
    asm volatile("mma.sync.aligned.m16n8k16.row.col.f32.f16.f16.f32 " \
                 "{%0,%1,%2,%3}, {%4,%5,%6,%7}, {%8,%9}, {%0,%1,%2,%3};" \
                 : "+f"((d)[0]), "+f"((d)[1]), "+f"((d)[2]), "+f"((d)[3]) \
                 : "r"((a)[0]), "r"((a)[1]), "r"((a)[2]), "r"((a)[3]), \
                   "r"((b)[0]), "r"((b)[1]))

__device__ __forceinline__ uint32_t packbf2(float a, float b) {
    uint32_t r;
    asm("cvt.rn.bf16x2.f32 %0, %1, %2;" : "=r"(r) : "f"(b), "f"(a));
    return r;
}
__device__ __forceinline__ uint32_t packh2(float a, float b) {
    uint32_t r;
    asm("cvt.rn.f16x2.f32 %0, %1, %2;" : "=r"(r) : "f"(b), "f"(a));
    return r;
}
__device__ __forceinline__ float bflow(uint32_t p)  { return __uint_as_float(p << 16); }
__device__ __forceinline__ float bfhigh(uint32_t p) { return __uint_as_float(p & 0xffff0000u); }
__device__ __forceinline__ uint32_t packsc(float s) {
    float hf = __bfloat162float(__float2bfloat16(s));
    return packbf2(s, s - hf);
}
__device__ __forceinline__ float fex2(float x) {
    float e;
    asm("ex2.approx.f32 %0, %1;" : "=f"(e) : "f"(x));
    return e;
}

// ---------------- conversions ----------------
__global__ __launch_bounds__(256) void convhl_k(const float* __restrict__ X,
                                                __nv_bfloat16* __restrict__ H,
                                                __nv_bfloat16* __restrict__ L)
{
    int i = (blockIdx.x * 256 + threadIdx.x) * 4;
    float4 v = *reinterpret_cast<const float4*>(X + i);
    float f[4] = {v.x, v.y, v.z, v.w};
    __nv_bfloat16 h[4], l[4];
#pragma unroll
    for (int j = 0; j < 4; j++) {
        h[j] = __float2bfloat16(f[j]);
        l[j] = __float2bfloat16(f[j] - __bfloat162float(h[j]));
    }
    *reinterpret_cast<uint2*>(H + i) = *reinterpret_cast<uint2*>(h);
    *reinterpret_cast<uint2*>(L + i) = *reinterpret_cast<uint2*>(l);
}

__global__ __launch_bounds__(256) void convwt_k(const float* __restrict__ w0,
                                                const float* __restrict__ w1,
                                                const float* __restrict__ w2,
                                                const float* __restrict__ w3,
                                                __nv_bfloat16* __restrict__ HtB,
                                                __nv_bfloat16* __restrict__ LtB)
{
    __shared__ float t[32][33];
    const int z = blockIdx.z;
    const float* W = (z == 0) ? w0 : (z == 1) ? w1 : (z == 2) ? w2 : w3;
    __nv_bfloat16* Ht = HtB + (size_t)z * HID * HID;
    __nv_bfloat16* Lt = LtB + (size_t)z * HID * HID;
    int n0 = blockIdx.x * 32, k0 = blockIdx.y * 32;
    int tx = threadIdx.x & 31, ty = threadIdx.x >> 5;
#pragma unroll
    for (int s = 0; s < 32; s += 8)
        t[ty + s][tx] = W[(size_t)(k0 + ty + s) * HID + n0 + tx];
    __syncthreads();
#pragma unroll
    for (int s = 0; s < 32; s += 8) {
        float v = t[tx][ty + s];
        __nv_bfloat16 h = __float2bfloat16(v);
        __nv_bfloat16 l = __float2bfloat16(v - __bfloat162float(h));
        size_t o = (size_t)(n0 + ty + s) * HID + k0 + tx;
        Ht[o] = h; Lt[o] = l;
    }
}

// ---------------- HMMA 3-term GEMM (unchanged) ----------------
#define GKC  32
#define GNC  (HID / GKC)
#define ARRB (128 * 80)
#define BUFB (4 * ARRB)
#define EPIP 129

__global__ __launch_bounds__(256) void gemmmma_k(const __nv_bfloat16* __restrict__ Ap,
                                                 const __nv_bfloat16* __restrict__ Alp,
                                                 const __nv_bfloat16* __restrict__ WhB,
                                                 const __nv_bfloat16* __restrict__ WlB,
                                                 float* __restrict__ C,
                                                 __half* __restrict__ Qh,
                                                 __half* __restrict__ Ql,
                                                 __half* __restrict__ Kg,
                                                 __half* __restrict__ Vg,
                                                 int qkv)
{
    extern __shared__ char dsm[];
    const uint32_t sbase = smem_u32(dsm);
    const int tid = threadIdx.x, wid = tid >> 5, lane = tid & 31;
    const int m0 = blockIdx.y * 128, n0 = blockIdx.x * 128;
    const int m0w = (wid & 1) * 64, n0w = (wid >> 1) * 32;
    const int z = qkv ? blockIdx.z : 0;
    const __nv_bfloat16* Bp  = WhB + (size_t)z * HID * HID;
    const __nv_bfloat16* Blp = WlB + (size_t)z * HID * HID;

    float acc[4][4][4];
#pragma unroll
    for (int i = 0; i < 4; i++)
#pragma unroll
        for (int j = 0; j < 4; j++)
#pragma unroll
            for (int r = 0; r < 4; r++) acc[i][j][r] = 0.f;

    auto load_chunk = [&](int c, int b) {
        const int koff = c * GKC;
        const uint32_t dst0 = sbase + b * BUFB;
#pragma unroll
        for (int l = 0; l < 8; l++) {
            int e = tid + l * 256;
            int arr = e >> 9, r = (e >> 2) & 127, q = e & 3;
            const __nv_bfloat16* G = (arr == 0) ? Ap : (arr == 1) ? Alp
                                   : (arr == 2) ? Bp : Blp;
            int t0 = (arr < 2) ? m0 : n0;
            CP_ASYNC16(dst0 + arr * ARRB + r * 80 + q * 16,
                       G + (size_t)(t0 + r) * HID + koff + q * 8);
        }
    };

    load_chunk(0, 0);
    CP_COMMIT();

    const int arow = lane & 15, acolb = (lane >> 4) * 16;
    const int brow = ((lane >> 4) << 3) + (lane & 7);
    const int bcolb = ((lane >> 3) & 1) * 16;

    for (int c = 0; c < GNC; c++) {
        const int b = c & 1;
        CP_WAIT0();
        __syncthreads();
        if (c + 1 < GNC) { load_chunk(c + 1, (c + 1) & 1); CP_COMMIT(); }

        const uint32_t bufb = sbase + b * BUFB;
#pragma unroll
        for (int kk = 0; kk < 2; kk++) {
            uint32_t ah[4][4], al[4][4], bh[4][2], bl[4][2];
            const int kb = kk * 32;
#pragma unroll
            for (int i = 0; i < 4; i++) {
                uint32_t ad = bufb + (m0w + i * 16 + arow) * 80 + acolb + kb;
                LDSM_X4(ah[i][0], ah[i][1], ah[i][2], ah[i][3], ad);
                LDSM_X4(al[i][0], al[i][1], al[i][2], al[i][3], ad + ARRB);
            }
            {
                uint32_t bd = bufb + 2 * ARRB + brow * 80 + bcolb + kb;
                uint32_t r0, r1, r2, r3;
                LDSM_X4(r0, r1, r2, r3, bd + n0w * 80);
                bh[0][0] = r0; bh[0][1] = r1; bh[1][0] = r2; bh[1][1] = r3;
                LDSM_X4(r0, r1, r2, r3, bd + (n0w + 16) * 80);
                bh[2][0] = r0; bh[2][1] = r1; bh[3][0] = r2; bh[3][1] = r3;
                LDSM_X4(r0, r1, r2, r3, bd + n0w * 80 + ARRB);
                bl[0][0] = r0; bl[0][1] = r1; bl[1][0] = r2; bl[1][1] = r3;
                LDSM_X4(r0, r1, r2, r3, bd + (n0w + 16) * 80 + ARRB);
                bl[2][0] = r0; bl[2][1] = r1; bl[3][0] = r2; bl[3][1] = r3;
            }
#pragma unroll
            for (int i = 0; i < 4; i++)
#pragma unroll
                for (int j = 0; j < 4; j++) {
                    MMA16816(acc[i][j], ah[i], bh[j]);
                    MMA16816(acc[i][j], ah[i], bl[j]);
                    MMA16816(acc[i][j], al[i], bh[j]);
                }
        }
    }
    __syncthreads();

    float* fsm = reinterpret_cast<float*>(dsm);
    const int r0w = m0w + (lane >> 2), c0w = n0w + (lane & 3) * 2;
#pragma unroll
    for (int i = 0; i < 4; i++)
#pragma unroll
        for (int j = 0; j < 4; j++) {
            int r = r0w + i * 16, cc = c0w + j * 8;
            fsm[r * EPIP + cc]           = acc[i][j][0];
            fsm[r * EPIP + cc + 1]       = acc[i][j][1];
            fsm[(r + 8) * EPIP + cc]     = acc[i][j][2];
            fsm[(r + 8) * EPIP + cc + 1] = acc[i][j][3];
        }
    __syncthreads();

    if (!qkv) {
#pragma unroll
        for (int l = 0; l < 64; l++) {
            int e = tid + l * 256;
            int r = e >> 7, cc = e & 127;
            C[(size_t)(m0 + r) * HID + n0 + cc] = fsm[r * EPIP + cc];
        }
    } else if (z == 0) {
#pragma unroll
        for (int l = 0; l < 32; l++) {
            int e = tid + l * 256;
            int r = e >> 6, c2 = (e & 63) * 2;
            float f0 = fsm[r * EPIP + c2], f1 = fsm[r * EPIP + c2 + 1];
            __half h0 = __float2half_rn(f0), h1 = __float2half_rn(f1);
            __half l0 = __float2half_rn(f0 - __half2float(h0));
            __half l1 = __float2half_rn(f1 - __half2float(h1));
            int n = n0 + c2;
            size_t o = ((size_t)(n >> 6) * S_LEN + m0 + r) * HDIM + (n & 63);
            *reinterpret_cast<__half2*>(Qh + o) = __halves2half2(h0, h1);
            *reinterpret_cast<__half2*>(Ql + o) = __halves2half2(l0, l1);
        }
    } else if (z == 1) {
#pragma unroll
        for (int l = 0; l < 32; l++) {
            int e = tid + l * 256;
            int r = e >> 6, c2 = (e & 63) * 2;
            float f0 = fsm[r * EPIP + c2], f1 = fsm[r * EPIP + c2 + 1];
            int n = n0 + c2;
            size_t o = ((size_t)(n >> 6) * S_LEN + m0 + r) * HDIM + (n & 63);
            *reinterpret_cast<__half2*>(Kg + o) =
                __halves2half2(__float2half_rn(f0), __float2half_rn(f1));
        }
    } else {
#pragma unroll
        for (int l = 0; l < 32; l++) {
            int e = tid + l * 256;
            int cc = e >> 6, rp = (e & 63) * 2;
            float f0 = fsm[rp * EPIP + cc], f1 = fsm[(rp + 1) * EPIP + cc];
            int n = n0 + cc;
            size_t o = ((size_t)(n >> 6) * HDIM + (n & 63)) * S_LEN + m0 + rp;
            *reinterpret_cast<__half2*>(Vg + o) =
                __halves2half2(__float2half_rn(f0), __float2half_rn(f1));
        }
    }
}

// ---- fp16 ring attention v6: warp-private 4-deep cp.async pipelines ----
// AQ=16, 128 thr, 2 CTAs/SM. No __syncthreads in QK/PV loops.
#define AQ      16
#define ROWB    4144
#define EP      1036
#define EBYTES  (AQ * ROWB)              // 66304
#define WTB     2304                     // warp tile: 16 rows x 144B
#define OFF_KV  EBYTES                   // 4 warps x 4 bufs x WTB = 36864
#define OFF_Q   (OFF_KV + 16 * WTB)      // 103168
#define QP2     144
#define OFF_DSH (OFF_Q + 2 * AQ * QP2)   // 107776
#define ASMEM   (OFF_DSH + 64)           // 107840

__global__ __launch_bounds__(128) void attn4_k(
    const __half* __restrict__ Qh, const __half* __restrict__ Ql,
    const __half* __restrict__ Kg, const __half* __restrict__ Vg,
    __nv_bfloat16* __restrict__ Oh, __nv_bfloat16* __restrict__ Ol)
{
    extern __shared__ char smraw[];
    float* dsh = reinterpret_cast<float*>(smraw + OFF_DSH);
    const uint32_t sb = smem_u32(smraw);

    const int tid = threadIdx.x, wid = tid >> 5, lane = tid & 31;
    const int g = lane >> 2, tg = lane & 3;
    const int h = blockIdx.y, q0 = blockIdx.x * AQ;
    const uint32_t kwb = sb + OFF_KV + wid * 4 * WTB;   // this warp's 4-buffer ring

    // warp-private stagers: 16 rows x 128B, 4 cp.async per lane
    auto stageK = [&](int blk, int c) {
        const uint32_t dst = kwb + (c & 3) * WTB;
        const __half* src = Kg + ((size_t)h * S_LEN + blk * 1024 + c * 64 + wid * 16) * HDIM;
#pragma unroll
        for (int i = 0; i < 4; i++) {
            int e = lane + i * 32;
            int r = e >> 3, q = e & 7;
            CP_ASYNC16(dst + r * 144 + q * 16, src + (size_t)r * HDIM + q * 8);
        }
    };
    auto stageV = [&](int blk, int c) {
        const uint32_t dst = kwb + (c & 3) * WTB;
        const __half* src = Vg + ((size_t)h * HDIM + wid * 16) * S_LEN + blk * 1024 + c * 64;
#pragma unroll
        for (int i = 0; i < 4; i++) {
            int e = lane + i * 32;
            int r = e >> 3, q = e & 7;
            CP_ASYNC16(dst + r * 144 + q * 16, src + (size_t)r * S_LEN + q * 8);
        }
    };

    if (tid < AQ) dsh[tid] = 0.f;
    {   // Q stage (cross-warp) as its own group
        int r = tid >> 3, q = tid & 7;
        const size_t go = ((size_t)h * S_LEN + q0 + r) * HDIM + q * 8;
        CP_ASYNC16(sb + OFF_Q + r * QP2 + q * 16, Qh + go);
        CP_ASYNC16(sb + OFF_Q + AQ * QP2 + r * QP2 + q * 16, Ql + go);
    }
    CP_COMMIT();
    // K prologue: chunks 0..2 of block 0 (3 groups)
    stageK(0, 0); CP_COMMIT();
    stageK(0, 1); CP_COMMIT();
    stageK(0, 2); CP_COMMIT();
    CP_WAIT3();          // Q group complete; K groups may be in flight
    __syncthreads();

    uint32_t qfh[4][4], qfl[4][4];
    {
        const uint32_t a0 = sb + OFF_Q + (lane & 15) * QP2 + (lane >> 4) * 16;
#pragma unroll
        for (int kt = 0; kt < 4; kt++) {
            LDSM_X4(qfh[kt][0], qfh[kt][1], qfh[kt][2], qfh[kt][3], a0 + kt * 32);
            LDSM_X4(qfl[kt][0], qfl[kt][1], qfl[kt][2], qfl[kt][3],
                    a0 + kt * 32 + AQ * QP2);
        }
    }

    float num[2][4];
#pragma unroll
    for (int n = 0; n < 2; n++)
#pragma unroll
        for (int r = 0; r < 4; r++) num[n][r] = 0.f;

    const int rL = ((lane >> 4) & 1) * 8 + (lane & 7);   // local 16-row frag row
    const int cB = ((lane >> 3) & 1) * 16;

    for (int blk = 0; blk < NBLK; blk++) {
        // ===== QK^T: warp-private pipeline, no CTA barriers =====
        for (int c = 0; c < 16; c++) {
            if (c + 3 < 16) stageK(blk, c + 3);
            CP_COMMIT();                 // (possibly empty group)
            CP_WAIT3();                  // chunk c complete
            const uint32_t kb = kwb + (c & 3) * WTB;

            float acc[2][4];
#pragma unroll
            for (int nt = 0; nt < 2; nt++)
#pragma unroll
                for (int r = 0; r < 4; r++) acc[nt][r] = 0.f;
#pragma unroll
            for (int kt = 0; kt < 4; kt++) {
                uint32_t bh[4];
                LDSM_X4(bh[0], bh[1], bh[2], bh[3], kb + rL * 144 + kt * 32 + cB);
                MMAH16816(acc[0], qfh[kt], &bh[0]);
                MMAH16816(acc[0], qfl[kt], &bh[0]);
                MMAH16816(acc[1], qfh[kt], &bh[2]);
                MMAH16816(acc[1], qfl[kt], &bh[2]);
            }
            uint32_t* ep = reinterpret_cast<uint32_t*>(smraw);
#pragma unroll
            for (int nt = 0; nt < 2; nt++) {
                int col = c * 64 + wid * 16 + nt * 8 + tg * 2;
                *reinterpret_cast<uint2*>(ep + g * EP + col) =
                    make_uint2(packsc(acc[nt][0] * 0.125f), packsc(acc[nt][1] * 0.125f));
                *reinterpret_cast<uint2*>(ep + (g + 8) * EP + col) =
                    make_uint2(packsc(acc[nt][2] * 0.125f), packsc(acc[nt][3] * 0.125f));
            }
        }
        // V prologue overlaps softmax (warp-private buffers, safe pre-barrier)
        stageV(blk, 0); CP_COMMIT();
        stageV(blk, 1); CP_COMMIT();
        stageV(blk, 2); CP_COMMIT();
        __syncthreads();   // all scores visible

        // ===== softmax: block-local max, E -> fp16 plane =====
#pragma unroll
        for (int rr = 0; rr < 4; rr++) {
            const int row = wid * 4 + rr;
            char* rowp = smraw + row * ROWB;
            uint4 pk[8];
            float m = -1e30f;
#pragma unroll
            for (int i = 0; i < 8; i++) {
                pk[i] = reinterpret_cast<uint4*>(rowp)[lane + 32 * i];
                float s0 = bflow(pk[i].x) + bfhigh(pk[i].x);
                float s1 = bflow(pk[i].y) + bfhigh(pk[i].y);
                float s2 = bflow(pk[i].z) + bfhigh(pk[i].z);
                float s3 = bflow(pk[i].w) + bfhigh(pk[i].w);
                m = fmaxf(m, fmaxf(fmaxf(s0, s1), fmaxf(s2, s3)));
            }
#pragma unroll
            for (int off = 16; off >= 1; off >>= 1)
                m = fmaxf(m, __shfl_xor_sync(0xffffffffu, m, off));
            const float mb = m * 1.4426950408889634f;
            float den = 0.f;
#pragma unroll
            for (int i = 0; i < 8; i++) {
                float e0 = fex2(fmaf(bflow(pk[i].x) + bfhigh(pk[i].x), 1.4426950408889634f, -mb));
                float e1 = fex2(fmaf(bflow(pk[i].y) + bfhigh(pk[i].y), 1.4426950408889634f, -mb));
                float e2 = fex2(fmaf(bflow(pk[i].z) + bfhigh(pk[i].z), 1.4426950408889634f, -mb));
                float e3 = fex2(fmaf(bflow(pk[i].w) + bfhigh(pk[i].w), 1.4426950408889634f, -mb));
                den += (e0 + e1) + (e2 + e3);
                reinterpret_cast<uint2*>(rowp)[lane + 32 * i] =
                    make_uint2(packh2(e0, e1), packh2(e2, e3));
            }
#pragma unroll
            for (int off = 16; off >= 1; off >>= 1)
                den += __shfl_xor_sync(0xffffffffu, den, off);
            if (lane == 0) dsh[row] += den;
        }
        __syncthreads();   // E plane + dsh visible

        // ===== PV: warp-private pipeline, no CTA barriers =====
        for (int c = 0; c < 16; c++) {
            if (c + 3 < 16) stageV(blk, c + 3);
            CP_COMMIT();
            CP_WAIT3();
            const uint32_t vb = kwb + (c & 3) * WTB;
            const uint32_t ebase = sb + (lane & 15) * ROWB + (lane >> 4) * 16 + c * 128;
#pragma unroll
            for (int u = 0; u < 4; u++) {
                uint32_t aH[4], bh[4];
                LDSM_X4(aH[0], aH[1], aH[2], aH[3], ebase + u * 32);
                LDSM_X4(bh[0], bh[1], bh[2], bh[3], vb + rL * 144 + u * 32 + cB);
                MMAH16816(num[0], aH, &bh[0]);
                MMAH16816(num[1], aH, &bh[2]);
            }
        }
        // next-block K prologue overlaps the barrier + next softmax wait
        if (blk < 3) {
            stageK(blk + 1, 0); CP_COMMIT();
            stageK(blk + 1, 1); CP_COMMIT();
            stageK(blk + 1, 2); CP_COMMIT();
        }
        __syncthreads();   // E buffer reusable for next QK's scores
    }

    // ---- epilogue: normalize, bf16 hi/lo out ----
    {
        const float id0 = 1.0f / dsh[g];
        const float id1 = 1.0f / dsh[g + 8];
#pragma unroll
        for (int nt = 0; nt < 2; nt++) {
            const int col = h * HDIM + wid * 16 + nt * 8 + tg * 2;
            float o0 = num[nt][0] * id0, o1 = num[nt][1] * id0;
            float o2 = num[nt][2] * id1, o3 = num[nt][3] * id1;
            uint32_t hp0 = packbf2(o0, o1);
            uint32_t lp0 = packbf2(o0 - bflow(hp0), o1 - bfhigh(hp0));
            uint32_t hp1 = packbf2(o2, o3);
            uint32_t lp1 = packbf2(o2 - bflow(hp1), o3 - bfhigh(hp1));
            size_t a0 = (size_t)(q0 + g) * HID + col;
            size_t a1 = (size_t)(q0 + g + 8) * HID + col;
            *reinterpret_cast<uint32_t*>(Oh + a0) = hp0;
            *reinterpret_cast<uint32_t*>(Ol + a0) = lp0;
            *reinterpret_cast<uint32_t*>(Oh + a1) = hp1;
            *reinterpret_cast<uint32_t*>(Ol + a1) = lp1;
        }
    }
}

// ---------------- launch ----------------
extern "C" void kernel_launch(void* const* d_in, const int* in_sizes, int n_in,
                              void* d_out, int out_size)
{
    const float* x = (const float*)d_in[0];
    float* out = (float*)d_out;

    __nv_bfloat16 *Xh, *Xl, *Ah, *Al, *Wh, *Wl;
    __half *Qh, *Ql, *Kg, *Vg;
    cudaGetSymbolAddress((void**)&Xh, g_Xh); cudaGetSymbolAddress((void**)&Xl, g_Xl);
    cudaGetSymbolAddress((void**)&Ah, g_Ah); cudaGetSymbolAddress((void**)&Al, g_Al);
    cudaGetSymbolAddress((void**)&Wh, g_Wh); cudaGetSymbolAddress((void**)&Wl, g_Wl);
    cudaGetSymbolAddress((void**)&Qh, g_Qh2); cudaGetSymbolAddress((void**)&Ql, g_Ql2);
    cudaGetSymbolAddress((void**)&Kg, g_K2);  cudaGetSymbolAddress((void**)&Vg, g_V2);

    const int gemm_smem = 2 * BUFB;
    cudaFuncSetAttribute(gemmmma_k, cudaFuncAttributeMaxDynamicSharedMemorySize, gemm_smem);
    cudaFuncSetAttribute(attn4_k, cudaFuncAttributeMaxDynamicSharedMemorySize, ASMEM);

    convhl_k<<<(S_LEN * HID) / 1024, 256>>>(x, Xh, Xl);
    convwt_k<<<dim3(HID / 32, HID / 32, 4), 256>>>((const float*)d_in[1], (const float*)d_in[2],
                                                   (const float*)d_in[3], (const float*)d_in[4],
                                                   Wh, Wl);

    gemmmma_k<<<dim3(HID / 128, S_LEN / 128, 3), 256, gemm_smem>>>(
        Xh, Xl, Wh, Wl, nullptr, Qh, Ql, Kg, Vg, 1);

    dim3 ag(S_LEN / AQ, HEADS);
    attn4_k<<<ag, 128, ASMEM>>>(Qh, Ql, Kg, Vg, Ah, Al);

    gemmmma_k<<<dim3(HID / 128, S_LEN / 128, 1), 256, gemm_smem>>>(
        Ah, Al, Wh + 3 * (size_t)HID * HID, Wl + 3 * (size_t)HID * HID,
        out, nullptr, nullptr, nullptr, nullptr, 0);
}

// round 13
// speedup vs baseline: 1.6699x; 1.0542x over previous
#include <cuda_runtime.h>
#include <cuda_bf16.h>
#include <cuda_fp16.h>
#include <cstdint>

#define S_LEN 4096
#define HID   1024
#define HEADS 16
#define HDIM  64
#define NBLK  4

__device__ __nv_bfloat16 g_Xh[S_LEN * HID], g_Xl[S_LEN * HID];
__device__ __nv_bfloat16 g_Ah[S_LEN * HID], g_Al[S_LEN * HID];   // attn out [s][hid]
__device__ __nv_bfloat16 g_Wh[4][HID * HID], g_Wl[4][HID * HID];
__device__ __half g_Qh2[S_LEN * HID], g_Ql2[S_LEN * HID];        // [h][s][d] fp16 hi/lo
__device__ __half g_K2[S_LEN * HID];                              // [h][s][d] fp16
__device__ __half g_V2[S_LEN * HID];                              // [h][d][s] fp16

__device__ __forceinline__ uint32_t smem_u32(const void* p) {
    uint32_t a;
    asm("{ .reg .u64 t; cvta.to.shared.u64 t, %1; cvt.u32.u64 %0, t; }" : "=r"(a) : "l"(p));
    return a;
}
#define CP_ASYNC16(dst, src) \
    asm volatile("cp.async.cg.shared.global [%0], [%1], 16;" :: "r"(dst), "l"(src))
#define CP_COMMIT() asm volatile("cp.async.commit_group;" ::: "memory")
#define CP_WAIT0()  asm volatile("cp.async.wait_group 0;" ::: "memory")
#define CP_WAIT3()  asm volatile("cp.async.wait_group 3;" ::: "memory")
#define LDSM_X4(r0, r1, r2, r3, addr) \
    asm volatile("ldmatrix.sync.aligned.m8n8.x4.shared.b16 {%0,%1,%2,%3}, [%4];" \
                 : "=r"(r0), "=r"(r1), "=r"(r2), "=r"(r3) : "r"(addr))
#define MMA16816(d, a, b) \
    asm volatile("mma.sync.aligned.m16n8k16.row.col.f32.bf16.bf16.f32 " \
                 "{%0,%1,%2,%3}, {%4,%5,%6,%7}, {%8,%9}, {%0,%1,%2,%3};" \
                 : "+f"((d)[0]), "+f"((d)[1]), "+f"((d)[2]), "+f"((d)[3]) \
                 : "r"((a)[0]), "r"((a)[1]), "r"((a)[2]), "r"((a)[3]), \
                   "r"((b)[0]), "r"((b)[1]))
#define MMAH16816(d, a, b) \
    asm volatile("mma.sync.aligned.m16n8k16.row.col.f32.f16.f16.f32 " \
                 "{%0,%1,%2,%3}, {%4,%5,%6,%7}, {%8,%9}, {%0,%1,%2,%3};" \
                 : "+f"((d)[0]), "+f"((d)[1]), "+f"((d)[2]), "+f"((d)[3]) \
                 : "r"((a)[0]), "r"((a)[1]), "r"((a)[2]), "r"((a)[3]), \
                   "r"((b)[0]), "r"((b)[1]))

__device__ __forceinline__ uint32_t packbf2(float a, float b) {
    uint32_t r;
    asm("cvt.rn.bf16x2.f32 %0, %1, %2;" : "=r"(r) : "f"(b), "f"(a));
    return r;
}
__device__ __forceinline__ uint32_t packh2(float a, float b) {
    uint32_t r;
    asm("cvt.rn.f16x2.f32 %0, %1, %2;" : "=r"(r) : "f"(b), "f"(a));
    return r;
}
__device__ __forceinline__ float bflow(uint32_t p)  { return __uint_as_float(p << 16); }
__device__ __forceinline__ float bfhigh(uint32_t p) { return __uint_as_float(p & 0xffff0000u); }
__device__ __forceinline__ float fex2(float x) {
    float e;
    asm("ex2.approx.f32 %0, %1;" : "=f"(e) : "f"(x));
    return e;
}

// ---------------- conversions ----------------
__global__ __launch_bounds__(256) void convhl_k(const float* __restrict__ X,
                                                __nv_bfloat16* __restrict__ H,
                                                __nv_bfloat16* __restrict__ L)
{
    int i = (blockIdx.x * 256 + threadIdx.x) * 4;
    float4 v = *reinterpret_cast<const float4*>(X + i);
    float f[4] = {v.x, v.y, v.z, v.w};
    __nv_bfloat16 h[4], l[4];
#pragma unroll
    for (int j = 0; j < 4; j++) {
        h[j] = __float2bfloat16(f[j]);
        l[j] = __float2bfloat16(f[j] - __bfloat162float(h[j]));
    }
    *reinterpret_cast<uint2*>(H + i) = *reinterpret_cast<uint2*>(h);
    *reinterpret_cast<uint2*>(L + i) = *reinterpret_cast<uint2*>(l);
}

__global__ __launch_bounds__(256) void convwt_k(const float* __restrict__ w0,
                                                const float* __restrict__ w1,
                                                const float* __restrict__ w2,
                                                const float* __restrict__ w3,
                                                __nv_bfloat16* __restrict__ HtB,
                                                __nv_bfloat16* __restrict__ LtB)
{
    __shared__ float t[32][33];
    const int z = blockIdx.z;
    const float* W = (z == 0) ? w0 : (z == 1) ? w1 : (z == 2) ? w2 : w3;
    __nv_bfloat16* Ht = HtB + (size_t)z * HID * HID;
    __nv_bfloat16* Lt = LtB + (size_t)z * HID * HID;
    int n0 = blockIdx.x * 32, k0 = blockIdx.y * 32;
    int tx = threadIdx.x & 31, ty = threadIdx.x >> 5;
#pragma unroll
    for (int s = 0; s < 32; s += 8)
        t[ty + s][tx] = W[(size_t)(k0 + ty + s) * HID + n0 + tx];
    __syncthreads();
#pragma unroll
    for (int s = 0; s < 32; s += 8) {
        float v = t[tx][ty + s];
        __nv_bfloat16 h = __float2bfloat16(v);
        __nv_bfloat16 l = __float2bfloat16(v - __bfloat162float(h));
        size_t o = (size_t)(n0 + ty + s) * HID + k0 + tx;
        Ht[o] = h; Lt[o] = l;
    }
}

// ---------------- HMMA 3-term GEMM (unchanged) ----------------
#define GKC  32
#define GNC  (HID / GKC)
#define ARRB (128 * 80)
#define BUFB (4 * ARRB)
#define EPIP 129

__global__ __launch_bounds__(256) void gemmmma_k(const __nv_bfloat16* __restrict__ Ap,
                                                 const __nv_bfloat16* __restrict__ Alp,
                                                 const __nv_bfloat16* __restrict__ WhB,
                                                 const __nv_bfloat16* __restrict__ WlB,
                                                 float* __restrict__ C,
                                                 __half* __restrict__ Qh,
                                                 __half* __restrict__ Ql,
                                                 __half* __restrict__ Kg,
                                                 __half* __restrict__ Vg,
                                                 int qkv)
{
    extern __shared__ char dsm[];
    const uint32_t sbase = smem_u32(dsm);
    const int tid = threadIdx.x, wid = tid >> 5, lane = tid & 31;
    const int m0 = blockIdx.y * 128, n0 = blockIdx.x * 128;
    const int m0w = (wid & 1) * 64, n0w = (wid >> 1) * 32;
    const int z = qkv ? blockIdx.z : 0;
    const __nv_bfloat16* Bp  = WhB + (size_t)z * HID * HID;
    const __nv_bfloat16* Blp = WlB + (size_t)z * HID * HID;

    float acc[4][4][4];
#pragma unroll
    for (int i = 0; i < 4; i++)
#pragma unroll
        for (int j = 0; j < 4; j++)
#pragma unroll
            for (int r = 0; r < 4; r++) acc[i][j][r] = 0.f;

    auto load_chunk = [&](int c, int b) {
        const int koff = c * GKC;
        const uint32_t dst0 = sbase + b * BUFB;
#pragma unroll
        for (int l = 0; l < 8; l++) {
            int e = tid + l * 256;
            int arr = e >> 9, r = (e >> 2) & 127, q = e & 3;
            const __nv_bfloat16* G = (arr == 0) ? Ap : (arr == 1) ? Alp
                                   : (arr == 2) ? Bp : Blp;
            int t0 = (arr < 2) ? m0 : n0;
            CP_ASYNC16(dst0 + arr * ARRB + r * 80 + q * 16,
                       G + (size_t)(t0 + r) * HID + koff + q * 8);
        }
    };

    load_chunk(0, 0);
    CP_COMMIT();

    const int arow = lane & 15, acolb = (lane >> 4) * 16;
    const int brow = ((lane >> 4) << 3) + (lane & 7);
    const int bcolb = ((lane >> 3) & 1) * 16;

    for (int c = 0; c < GNC; c++) {
        const int b = c & 1;
        CP_WAIT0();
        __syncthreads();
        if (c + 1 < GNC) { load_chunk(c + 1, (c + 1) & 1); CP_COMMIT(); }

        const uint32_t bufb = sbase + b * BUFB;
#pragma unroll
        for (int kk = 0; kk < 2; kk++) {
            uint32_t ah[4][4], al[4][4], bh[4][2], bl[4][2];
            const int kb = kk * 32;
#pragma unroll
            for (int i = 0; i < 4; i++) {
                uint32_t ad = bufb + (m0w + i * 16 + arow) * 80 + acolb + kb;
                LDSM_X4(ah[i][0], ah[i][1], ah[i][2], ah[i][3], ad);
                LDSM_X4(al[i][0], al[i][1], al[i][2], al[i][3], ad + ARRB);
            }
            {
                uint32_t bd = bufb + 2 * ARRB + brow * 80 + bcolb + kb;
                uint32_t r0, r1, r2, r3;
                LDSM_X4(r0, r1, r2, r3, bd + n0w * 80);
                bh[0][0] = r0; bh[0][1] = r1; bh[1][0] = r2; bh[1][1] = r3;
                LDSM_X4(r0, r1, r2, r3, bd + (n0w + 16) * 80);
                bh[2][0] = r0; bh[2][1] = r1; bh[3][0] = r2; bh[3][1] = r3;
                LDSM_X4(r0, r1, r2, r3, bd + n0w * 80 + ARRB);
                bl[0][0] = r0; bl[0][1] = r1; bl[1][0] = r2; bl[1][1] = r3;
                LDSM_X4(r0, r1, r2, r3, bd + (n0w + 16) * 80 + ARRB);
                bl[2][0] = r0; bl[2][1] = r1; bl[3][0] = r2; bl[3][1] = r3;
            }
#pragma unroll
            for (int i = 0; i < 4; i++)
#pragma unroll
                for (int j = 0; j < 4; j++) {
                    MMA16816(acc[i][j], ah[i], bh[j]);
                    MMA16816(acc[i][j], ah[i], bl[j]);
                    MMA16816(acc[i][j], al[i], bh[j]);
                }
        }
    }
    __syncthreads();

    float* fsm = reinterpret_cast<float*>(dsm);
    const int r0w = m0w + (lane >> 2), c0w = n0w + (lane & 3) * 2;
#pragma unroll
    for (int i = 0; i < 4; i++)
#pragma unroll
        for (int j = 0; j < 4; j++) {
            int r = r0w + i * 16, cc = c0w + j * 8;
            fsm[r * EPIP + cc]           = acc[i][j][0];
            fsm[r * EPIP + cc + 1]       = acc[i][j][1];
            fsm[(r + 8) * EPIP + cc]     = acc[i][j][2];
            fsm[(r + 8) * EPIP + cc + 1] = acc[i][j][3];
        }
    __syncthreads();

    if (!qkv) {
#pragma unroll
        for (int l = 0; l < 64; l++) {
            int e = tid + l * 256;
            int r = e >> 7, cc = e & 127;
            C[(size_t)(m0 + r) * HID + n0 + cc] = fsm[r * EPIP + cc];
        }
    } else if (z == 0) {
#pragma unroll
        for (int l = 0; l < 32; l++) {
            int e = tid + l * 256;
            int r = e >> 6, c2 = (e & 63) * 2;
            float f0 = fsm[r * EPIP + c2], f1 = fsm[r * EPIP + c2 + 1];
            __half h0 = __float2half_rn(f0), h1 = __float2half_rn(f1);
            __half l0 = __float2half_rn(f0 - __half2float(h0));
            __half l1 = __float2half_rn(f1 - __half2float(h1));
            int n = n0 + c2;
            size_t o = ((size_t)(n >> 6) * S_LEN + m0 + r) * HDIM + (n & 63);
            *reinterpret_cast<__half2*>(Qh + o) = __halves2half2(h0, h1);
            *reinterpret_cast<__half2*>(Ql + o) = __halves2half2(l0, l1);
        }
    } else if (z == 1) {
#pragma unroll
        for (int l = 0; l < 32; l++) {
            int e = tid + l * 256;
            int r = e >> 6, c2 = (e & 63) * 2;
            float f0 = fsm[r * EPIP + c2], f1 = fsm[r * EPIP + c2 + 1];
            int n = n0 + c2;
            size_t o = ((size_t)(n >> 6) * S_LEN + m0 + r) * HDIM + (n & 63);
            *reinterpret_cast<__half2*>(Kg + o) =
                __halves2half2(__float2half_rn(f0), __float2half_rn(f1));
        }
    } else {
#pragma unroll
        for (int l = 0; l < 32; l++) {
            int e = tid + l * 256;
            int cc = e >> 6, rp = (e & 63) * 2;
            float f0 = fsm[rp * EPIP + cc], f1 = fsm[(rp + 1) * EPIP + cc];
            int n = n0 + cc;
            size_t o = ((size_t)(n >> 6) * HDIM + (n & 63)) * S_LEN + m0 + rp;
            *reinterpret_cast<__half2*>(Vg + o) =
                __halves2half2(__float2half_rn(f0), __float2half_rn(f1));
        }
    }
}

// ---- fp16 ring attention v7: warp-private pipelines + raw f32 scores ----
// AQ=16, 128 thr, 2 CTAs/SM. Batched LDSM ahead of MMA chains.
#define AQ      16
#define ROWB    4144
#define EP      1036
#define EBYTES  (AQ * ROWB)              // 66304
#define WTB     2304                     // warp tile: 16 rows x 144B
#define OFF_KV  EBYTES                   // 4 warps x 4 bufs x WTB = 36864
#define OFF_Q   (OFF_KV + 16 * WTB)      // 103168
#define QP2     144
#define OFF_DSH (OFF_Q + 2 * AQ * QP2)   // 107776
#define ASMEM   (OFF_DSH + 64)           // 107840

__global__ __launch_bounds__(128) void attn5_k(
    const __half* __restrict__ Qh, const __half* __restrict__ Ql,
    const __half* __restrict__ Kg, const __half* __restrict__ Vg,
    __nv_bfloat16* __restrict__ Oh, __nv_bfloat16* __restrict__ Ol)
{
    extern __shared__ char smraw[];
    float* dsh = reinterpret_cast<float*>(smraw + OFF_DSH);
    const uint32_t sb = smem_u32(smraw);

    const int tid = threadIdx.x, wid = tid >> 5, lane = tid & 31;
    const int g = lane >> 2, tg = lane & 3;
    const int h = blockIdx.y, q0 = blockIdx.x * AQ;
    const uint32_t kwb = sb + OFF_KV + wid * 4 * WTB;

    auto stageK = [&](int blk, int c) {
        const uint32_t dst = kwb + (c & 3) * WTB;
        const __half* src = Kg + ((size_t)h * S_LEN + blk * 1024 + c * 64 + wid * 16) * HDIM;
#pragma unroll
        for (int i = 0; i < 4; i++) {
            int e = lane + i * 32;
            int r = e >> 3, q = e & 7;
            CP_ASYNC16(dst + r * 144 + q * 16, src + (size_t)r * HDIM + q * 8);
        }
    };
    auto stageV = [&](int blk, int c) {
        const uint32_t dst = kwb + (c & 3) * WTB;
        const __half* src = Vg + ((size_t)h * HDIM + wid * 16) * S_LEN + blk * 1024 + c * 64;
#pragma unroll
        for (int i = 0; i < 4; i++) {
            int e = lane + i * 32;
            int r = e >> 3, q = e & 7;
            CP_ASYNC16(dst + r * 144 + q * 16, src + (size_t)r * S_LEN + q * 8);
        }
    };

    if (tid < AQ) dsh[tid] = 0.f;
    {
        int r = tid >> 3, q = tid & 7;
        const size_t go = ((size_t)h * S_LEN + q0 + r) * HDIM + q * 8;
        CP_ASYNC16(sb + OFF_Q + r * QP2 + q * 16, Qh + go);
        CP_ASYNC16(sb + OFF_Q + AQ * QP2 + r * QP2 + q * 16, Ql + go);
    }
    CP_COMMIT();
    stageK(0, 0); CP_COMMIT();
    stageK(0, 1); CP_COMMIT();
    stageK(0, 2); CP_COMMIT();
    CP_WAIT3();
    __syncthreads();

    uint32_t qfh[4][4], qfl[4][4];
    {
        const uint32_t a0 = sb + OFF_Q + (lane & 15) * QP2 + (lane >> 4) * 16;
#pragma unroll
        for (int kt = 0; kt < 4; kt++) {
            LDSM_X4(qfh[kt][0], qfh[kt][1], qfh[kt][2], qfh[kt][3], a0 + kt * 32);
            LDSM_X4(qfl[kt][0], qfl[kt][1], qfl[kt][2], qfl[kt][3],
                    a0 + kt * 32 + AQ * QP2);
        }
    }

    float num[2][4];
#pragma unroll
    for (int n = 0; n < 2; n++)
#pragma unroll
        for (int r = 0; r < 4; r++) num[n][r] = 0.f;

    const int rL = ((lane >> 4) & 1) * 8 + (lane & 7);
    const int cB = ((lane >> 3) & 1) * 16;

    for (int blk = 0; blk < NBLK; blk++) {
        // ===== QK^T: warp-private pipeline, batched LDSM, raw f32 scores =====
        for (int c = 0; c < 16; c++) {
            if (c + 3 < 16) stageK(blk, c + 3);
            CP_COMMIT();
            CP_WAIT3();
            const uint32_t kb = kwb + (c & 3) * WTB;

            uint32_t bh[4][4];
#pragma unroll
            for (int kt = 0; kt < 4; kt++)
                LDSM_X4(bh[kt][0], bh[kt][1], bh[kt][2], bh[kt][3],
                        kb + rL * 144 + kt * 32 + cB);

            float acc[2][4];
#pragma unroll
            for (int nt = 0; nt < 2; nt++)
#pragma unroll
                for (int r = 0; r < 4; r++) acc[nt][r] = 0.f;
#pragma unroll
            for (int kt = 0; kt < 4; kt++) {
                MMAH16816(acc[0], qfh[kt], &bh[kt][0]);
                MMAH16816(acc[0], qfl[kt], &bh[kt][0]);
                MMAH16816(acc[1], qfh[kt], &bh[kt][2]);
                MMAH16816(acc[1], qfl[kt], &bh[kt][2]);
            }
            float* ep = reinterpret_cast<float*>(smraw);
#pragma unroll
            for (int nt = 0; nt < 2; nt++) {
                int col = c * 64 + wid * 16 + nt * 8 + tg * 2;
                *reinterpret_cast<float2*>(ep + g * EP + col) =
                    make_float2(acc[nt][0] * 0.125f, acc[nt][1] * 0.125f);
                *reinterpret_cast<float2*>(ep + (g + 8) * EP + col) =
                    make_float2(acc[nt][2] * 0.125f, acc[nt][3] * 0.125f);
            }
        }
        stageV(blk, 0); CP_COMMIT();
        stageV(blk, 1); CP_COMMIT();
        stageV(blk, 2); CP_COMMIT();
        __syncthreads();   // all scores visible

        // ===== softmax: raw f32 in, fp16 E plane out =====
#pragma unroll
        for (int rr = 0; rr < 4; rr++) {
            const int row = wid * 4 + rr;
            char* rowp = smraw + row * ROWB;
            float4 v[8];
            float m = -1e30f;
#pragma unroll
            for (int i = 0; i < 8; i++) {
                v[i] = reinterpret_cast<float4*>(rowp)[lane + 32 * i];
                m = fmaxf(m, fmaxf(fmaxf(v[i].x, v[i].y), fmaxf(v[i].z, v[i].w)));
            }
#pragma unroll
            for (int off = 16; off >= 1; off >>= 1)
                m = fmaxf(m, __shfl_xor_sync(0xffffffffu, m, off));
            const float mb = m * 1.4426950408889634f;
            float den = 0.f;
#pragma unroll
            for (int i = 0; i < 8; i++) {
                float e0 = fex2(fmaf(v[i].x, 1.4426950408889634f, -mb));
                float e1 = fex2(fmaf(v[i].y, 1.4426950408889634f, -mb));
                float e2 = fex2(fmaf(v[i].z, 1.4426950408889634f, -mb));
                float e3 = fex2(fmaf(v[i].w, 1.4426950408889634f, -mb));
                den += (e0 + e1) + (e2 + e3);
                reinterpret_cast<uint2*>(rowp)[lane + 32 * i] =
                    make_uint2(packh2(e0, e1), packh2(e2, e3));
            }
#pragma unroll
            for (int off = 16; off >= 1; off >>= 1)
                den += __shfl_xor_sync(0xffffffffu, den, off);
            if (lane == 0) dsh[row] += den;
        }
        __syncthreads();   // E plane + dsh visible

        // ===== PV: warp-private pipeline, batched LDSM =====
        for (int c = 0; c < 16; c++) {
            if (c + 3 < 16) stageV(blk, c + 3);
            CP_COMMIT();
            CP_WAIT3();
            const uint32_t vb = kwb + (c & 3) * WTB;
            const uint32_t ebase = sb + (lane & 15) * ROWB + (lane >> 4) * 16 + c * 128;

            uint32_t aH[4][4], bv[4][4];
#pragma unroll
            for (int u = 0; u < 4; u++) {
                LDSM_X4(aH[u][0], aH[u][1], aH[u][2], aH[u][3], ebase + u * 32);
                LDSM_X4(bv[u][0], bv[u][1], bv[u][2], bv[u][3],
                        vb + rL * 144 + u * 32 + cB);
            }
#pragma unroll
            for (int u = 0; u < 4; u++) {
                MMAH16816(num[0], aH[u], &bv[u][0]);
                MMAH16816(num[1], aH[u], &bv[u][2]);
            }
        }
        if (blk < 3) {
            stageK(blk + 1, 0); CP_COMMIT();
            stageK(blk + 1, 1); CP_COMMIT();
            stageK(blk + 1, 2); CP_COMMIT();
        }
        __syncthreads();
    }

    // ---- epilogue: normalize, bf16 hi/lo out ----
    {
        const float id0 = 1.0f / dsh[g];
        const float id1 = 1.0f / dsh[g + 8];
#pragma unroll
        for (int nt = 0; nt < 2; nt++) {
            const int col = h * HDIM + wid * 16 + nt * 8 + tg * 2;
            float o0 = num[nt][0] * id0, o1 = num[nt][1] * id0;
            float o2 = num[nt][2] * id1, o3 = num[nt][3] * id1;
            uint32_t hp0 = packbf2(o0, o1);
            uint32_t lp0 = packbf2(o0 - bflow(hp0), o1 - bfhigh(hp0));
            uint32_t hp1 = packbf2(o2, o3);
            uint32_t lp1 = packbf2(o2 - bflow(hp1), o3 - bfhigh(hp1));
            size_t a0 = (size_t)(q0 + g) * HID + col;
            size_t a1 = (size_t)(q0 + g + 8) * HID + col;
            *reinterpret_cast<uint32_t*>(Oh + a0) = hp0;
            *reinterpret_cast<uint32_t*>(Ol + a0) = lp0;
            *reinterpret_cast<uint32_t*>(Oh + a1) = hp1;
            *reinterpret_cast<uint32_t*>(Ol + a1) = lp1;
        }
    }
}

// ---------------- launch ----------------
extern "C" void kernel_launch(void* const* d_in, const int* in_sizes, int n_in,
                              void* d_out, int out_size)
{
    const float* x = (const float*)d_in[0];
    float* out = (float*)d_out;

    __nv_bfloat16 *Xh, *Xl, *Ah, *Al, *Wh, *Wl;
    __half *Qh, *Ql, *Kg, *Vg;
    cudaGetSymbolAddress((void**)&Xh, g_Xh); cudaGetSymbolAddress((void**)&Xl, g_Xl);
    cudaGetSymbolAddress((void**)&Ah, g_Ah); cudaGetSymbolAddress((void**)&Al, g_Al);
    cudaGetSymbolAddress((void**)&Wh, g_Wh); cudaGetSymbolAddress((void**)&Wl, g_Wl);
    cudaGetSymbolAddress((void**)&Qh, g_Qh2); cudaGetSymbolAddress((void**)&Ql, g_Ql2);
    cudaGetSymbolAddress((void**)&Kg, g_K2);  cudaGetSymbolAddress((void**)&Vg, g_V2);

    const int gemm_smem = 2 * BUFB;
    cudaFuncSetAttribute(gemmmma_k, cudaFuncAttributeMaxDynamicSharedMemorySize, gemm_smem);
    cudaFuncSetAttribute(attn5_k, cudaFuncAttributeMaxDynamicSharedMemorySize, ASMEM);

    convhl_k<<<(S_LEN * HID) / 1024, 256>>>(x, Xh, Xl);
    convwt_k<<<dim3(HID / 32, HID / 32, 4), 256>>>((const float*)d_in[1], (const float*)d_in[2],
                                                   (const float*)d_in[3], (const float*)d_in[4],
                                                   Wh, Wl);

    gemmmma_k<<<dim3(HID / 128, S_LEN / 128, 3), 256, gemm_smem>>>(
        Xh, Xl, Wh, Wl, nullptr, Qh, Ql, Kg, Vg, 1);

    dim3 ag(S_LEN / AQ, HEADS);
    attn5_k<<<ag, 128, ASMEM>>>(Qh, Ql, Kg, Vg, Ah, Al);

    gemmmma_k<<<dim3(HID / 128, S_LEN / 128, 1), 256, gemm_smem>>>(
        Ah, Al, Wh + 3 * (size_t)HID * HID, Wl + 3 * (size_t)HID * HID,
        out, nullptr, nullptr, nullptr, nullptr, 0);
}